// round 1
// baseline (speedup 1.0000x reference)
#include <cuda_runtime.h>
#include <math.h>

#define Dm   768
#define Tt   4096
#define Bb   4
#define MTOT (Bb * Tt)   // 16384

// ---------------- scratch (static __device__ — no allocations) ----------------
__device__ float g_y  [MTOT * Dm];          // LN output (reused for LN1 and LN2)
__device__ float g_q  [MTOT * Dm];
__device__ float g_k  [MTOT * Dm];
__device__ float g_v  [MTOT * Dm];
__device__ float g_att[MTOT * Dm];
__device__ float g_h  [MTOT * Dm];
__device__ float g_s  [(size_t)Bb * Tt * Tt];   // 256 MB scores

// ---------------- block reductions (256 threads) ----------------
__device__ __forceinline__ float blockSum(float v) {
    __shared__ float red[8];
    #pragma unroll
    for (int o = 16; o > 0; o >>= 1) v += __shfl_xor_sync(0xffffffffu, v, o);
    __syncthreads();
    if ((threadIdx.x & 31) == 0) red[threadIdx.x >> 5] = v;
    __syncthreads();
    float r = red[0];
    #pragma unroll
    for (int i = 1; i < 8; i++) r += red[i];
    return r;
}

__device__ __forceinline__ float blockMax(float v) {
    __shared__ float redm[8];
    #pragma unroll
    for (int o = 16; o > 0; o >>= 1) v = fmaxf(v, __shfl_xor_sync(0xffffffffu, v, o));
    __syncthreads();
    if ((threadIdx.x & 31) == 0) redm[threadIdx.x >> 5] = v;
    __syncthreads();
    float r = redm[0];
    #pragma unroll
    for (int i = 1; i < 8; i++) r = fmaxf(r, redm[i]);
    return r;
}

// ---------------- LayerNorm (faithful to buggy reference) ----------------
// out = (x - mu/sqrt(var)) * gamma + beta, var with ddof=1
__global__ void ln_kernel(const float* __restrict__ x, const float* __restrict__ g,
                          const float* __restrict__ b, float* __restrict__ out) {
    size_t row = blockIdx.x;
    const float* xr = x + row * Dm;
    int tid = threadIdx.x;
    float v0 = xr[tid], v1 = xr[tid + 256], v2 = xr[tid + 512];
    float mu = blockSum(v0 + v1 + v2) * (1.0f / Dm);
    float d0 = v0 - mu, d1 = v1 - mu, d2 = v2 - mu;
    float var = blockSum(d0 * d0 + d1 * d1 + d2 * d2) * (1.0f / (Dm - 1));
    float c = mu / sqrtf(var);           // the reference's bug, reproduced exactly
    float* orow = out + row * Dm;
    orow[tid]       = (v0 - c) * g[tid]       + b[tid];
    orow[tid + 256] = (v1 - c) * g[tid + 256] + b[tid + 256];
    orow[tid + 512] = (v2 - c) * g[tid + 512] + b[tid + 512];
}

// ---------------- row softmax over 4096 ----------------
__global__ void softmax_kernel(float* __restrict__ S) {
    size_t row = blockIdx.x;
    float* sr = S + row * (size_t)Tt;
    int tid = threadIdx.x;
    float v[16];
    float m = -1e30f;
    #pragma unroll
    for (int i = 0; i < 16; i++) { v[i] = sr[tid + i * 256]; m = fmaxf(m, v[i]); }
    m = blockMax(m);
    float s = 0.f;
    #pragma unroll
    for (int i = 0; i < 16; i++) { v[i] = __expf(v[i] - m); s += v[i]; }
    s = blockSum(s);
    float inv = 1.0f / s;
    #pragma unroll
    for (int i = 0; i < 16; i++) sr[tid + i * 256] = v[i] * inv;
}

// ---------------- generic batched SGEMM 128x128x8, 8x8 micro-tile ----------------
// C[z] = alpha * A[z] @ op(B[z]) (+bias) (relu?) (+res)
// TRANSB=false: B is [K,N] row-major (ldb = N-stride). TRANSB=true: B is [N,K] row-major.
template <bool TRANSB, bool RELU>
__global__ __launch_bounds__(256, 2)
void sgemm(const float* __restrict__ A, const float* __restrict__ B,
           const float* __restrict__ bias, const float* __restrict__ res,
           float* __restrict__ C,
           int K, int lda, int ldb, int ldc,
           size_t aStride, size_t bStride, size_t cStride, float alpha) {
    __shared__ float As[8][128];
    __shared__ float Bs[8][128];
    const int tid = threadIdx.x;
    const int bm = blockIdx.y * 128, bn = blockIdx.x * 128;
    const float* Ab = A + aStride * blockIdx.z;
    const float* Bp = B + bStride * blockIdx.z;

    const int aRow = tid >> 1, aCol = (tid & 1) * 4;
    int bRow, bCol;
    if (TRANSB) { bRow = tid >> 1; bCol = (tid & 1) * 4; }
    else        { bRow = tid >> 5; bCol = (tid & 31) * 4; }
    const int row0 = (tid >> 4) * 8, col0 = (tid & 15) * 8;

    float acc[8][8] = {};

    for (int k0 = 0; k0 < K; k0 += 8) {
        float4 av = *(const float4*)(Ab + (size_t)(bm + aRow) * lda + k0 + aCol);
        As[aCol + 0][aRow] = av.x;
        As[aCol + 1][aRow] = av.y;
        As[aCol + 2][aRow] = av.z;
        As[aCol + 3][aRow] = av.w;
        if (TRANSB) {
            float4 bv = *(const float4*)(Bp + (size_t)(bn + bRow) * ldb + k0 + bCol);
            Bs[bCol + 0][bRow] = bv.x;
            Bs[bCol + 1][bRow] = bv.y;
            Bs[bCol + 2][bRow] = bv.z;
            Bs[bCol + 3][bRow] = bv.w;
        } else {
            float4 bv = *(const float4*)(Bp + (size_t)(k0 + bRow) * ldb + bn + bCol);
            *(float4*)&Bs[bRow][bCol] = bv;
        }
        __syncthreads();
        #pragma unroll
        for (int kk = 0; kk < 8; kk++) {
            float4 a0 = *(const float4*)&As[kk][row0];
            float4 a1 = *(const float4*)&As[kk][row0 + 4];
            float4 b0 = *(const float4*)&Bs[kk][col0];
            float4 b1 = *(const float4*)&Bs[kk][col0 + 4];
            float ar[8] = {a0.x, a0.y, a0.z, a0.w, a1.x, a1.y, a1.z, a1.w};
            float br[8] = {b0.x, b0.y, b0.z, b0.w, b1.x, b1.y, b1.z, b1.w};
            #pragma unroll
            for (int i = 0; i < 8; i++)
                #pragma unroll
                for (int j = 0; j < 8; j++)
                    acc[i][j] += ar[i] * br[j];
        }
        __syncthreads();
    }

    float* Cb = C + cStride * blockIdx.z;
    const float* Rb = res ? res + cStride * blockIdx.z : (const float*)0;
    #pragma unroll
    for (int i = 0; i < 8; i++) {
        size_t roff = (size_t)(bm + row0 + i) * ldc + bn + col0;
        #pragma unroll
        for (int j = 0; j < 8; j++) {
            float vv = acc[i][j] * alpha;
            if (bias) vv += bias[bn + col0 + j];
            if (RELU) vv = fmaxf(vv, 0.0f);
            if (Rb)   vv += Rb[roff + j];
            Cb[roff + j] = vv;
        }
    }
}

// ---------------- launch ----------------
extern "C" void kernel_launch(void* const* d_in, const int* in_sizes, int n_in,
                              void* d_out, int out_size) {
    const float* x     = (const float*)d_in[0];
    const float* ln1_g = (const float*)d_in[1];
    const float* ln1_b = (const float*)d_in[2];
    const float* wq    = (const float*)d_in[3];
    const float* wk    = (const float*)d_in[4];
    const float* wv    = (const float*)d_in[5];
    const float* ln2_g = (const float*)d_in[6];
    const float* ln2_b = (const float*)d_in[7];
    const float* fc1_w = (const float*)d_in[8];
    const float* fc1_b = (const float*)d_in[9];
    const float* fc2_w = (const float*)d_in[10];
    const float* fc2_b = (const float*)d_in[11];
    float* out = (float*)d_out;

    float *y, *q, *k, *v, *att, *h, *s;
    cudaGetSymbolAddress((void**)&y,   g_y);
    cudaGetSymbolAddress((void**)&q,   g_q);
    cudaGetSymbolAddress((void**)&k,   g_k);
    cudaGetSymbolAddress((void**)&v,   g_v);
    cudaGetSymbolAddress((void**)&att, g_att);
    cudaGetSymbolAddress((void**)&h,   g_h);
    cudaGetSymbolAddress((void**)&s,   g_s);

    const size_t sTD = (size_t)Tt * Dm;   // per-batch stride of [T,D] tensors
    const size_t sTT = (size_t)Tt * Tt;   // per-batch stride of scores
    const float scale = 1.0f / sqrtf((float)Dm);

    // 1. LN1
    ln_kernel<<<MTOT, 256>>>(x, ln1_g, ln1_b, y);

    // 2. Q,K,V projections: [16384,768] @ [768,768] (NN: wq is [K=D, N=D])
    dim3 gproj(Dm / 128, MTOT / 128, 1);
    sgemm<false, false><<<gproj, 256>>>(y, wq, 0, 0, q, Dm, Dm, Dm, Dm, 0, 0, 0, 1.0f);
    sgemm<false, false><<<gproj, 256>>>(y, wk, 0, 0, k, Dm, Dm, Dm, Dm, 0, 0, 0, 1.0f);
    sgemm<false, false><<<gproj, 256>>>(y, wv, 0, 0, v, Dm, Dm, Dm, Dm, 0, 0, 0, 1.0f);

    // 3. scores = scale * Q @ K^T, per batch (NT)
    dim3 gsc(Tt / 128, Tt / 128, Bb);
    sgemm<true, false><<<gsc, 256>>>(q, k, 0, 0, s, Dm, Dm, Dm, Tt, sTD, sTD, sTT, scale);

    // 4. softmax rows
    softmax_kernel<<<Bb * Tt, 256>>>(s);

    // 5. att = A @ V, per batch (NN: V is [K=T, N=D])
    dim3 gav(Dm / 128, Tt / 128, Bb);
    sgemm<false, false><<<gav, 256>>>(s, v, 0, 0, att, Tt, Tt, Dm, Dm, sTT, sTD, sTD, 1.0f);

    // 6. LN2
    ln_kernel<<<MTOT, 256>>>(att, ln2_g, ln2_b, y);

    // 7. MLP fc1: NT ([O,D] weights), +bias, ReLU
    sgemm<true, true><<<gproj, 256>>>(y, fc1_w, fc1_b, 0, h, Dm, Dm, Dm, Dm, 0, 0, 0, 1.0f);

    // 8. MLP fc2: NT, +bias, +residual x -> out
    sgemm<true, false><<<gproj, 256>>>(h, fc2_w, fc2_b, x, out, Dm, Dm, Dm, Dm, 0, 0, 0, 1.0f);
}

// round 4
// speedup vs baseline: 2.0362x; 2.0362x over previous
#include <cuda_runtime.h>
#include <cstdint>
#include <math.h>

#define Dm   768
#define Tt   4096
#define NB   4
#define MTOT (NB * Tt)   // 16384

// ---------------- scratch (static __device__ — no allocations) ----------------
__device__ float g_y  [MTOT * Dm];
__device__ float g_q  [MTOT * Dm];
__device__ float g_k  [MTOT * Dm];
__device__ float g_v  [MTOT * Dm];
__device__ float g_att[MTOT * Dm];
__device__ float g_h  [MTOT * Dm];          // doubles as V^T scratch before fc1
__device__ float g_wt [3 * Dm * Dm];        // wq^T, wk^T, wv^T
__device__ float g_s  [(size_t)NB * Tt * Tt];   // 256 MB scores

// ================= helpers =================
__device__ __forceinline__ uint32_t smem_u32(const void* p) {
    uint32_t a;
    asm("{ .reg .u64 t; cvta.to.shared.u64 t, %1; cvt.u32.u64 %0, t; }" : "=r"(a) : "l"(p));
    return a;
}

#define CP_ASYNC16(dst, src) \
    asm volatile("cp.async.cg.shared.global [%0], [%1], 16;" :: "r"(dst), "l"(src))
#define CP_COMMIT() asm volatile("cp.async.commit_group;" ::: "memory")
#define CP_WAIT(n)  asm volatile("cp.async.wait_group %0;" :: "n"(n) : "memory")

#define MMA_TF32(d, a, b) \
    asm volatile("mma.sync.aligned.m16n8k8.row.col.f32.tf32.tf32.f32 " \
        "{%0,%1,%2,%3}, {%4,%5,%6,%7}, {%8,%9}, {%0,%1,%2,%3};" \
        : "+f"((d)[0]), "+f"((d)[1]), "+f"((d)[2]), "+f"((d)[3]) \
        : "r"((a)[0]), "r"((a)[1]), "r"((a)[2]), "r"((a)[3]), \
          "r"((b)[0]), "r"((b)[1]))

// swizzled float offset inside a [128 rows x 32 floats] tile
__device__ __forceinline__ int sw_addr(int r, int c) {
    return r * 32 + ((((c >> 2) ^ (r & 7)) << 2) | (c & 3));
}

// ================= tf32 mma.sync GEMM =================
// NT: C[M,N] = alpha * A[M,K] @ B[N,K]^T  (+bias)(relu)(+res)
// 256 threads, CTA tile 128x128, warp tile 64x32, K-chunk 32, 2-stage cp.async.
template <bool RELU>
__global__ __launch_bounds__(256)
void gemm_mma(const float* __restrict__ A, const float* __restrict__ B,
              const float* __restrict__ bias, const float* __restrict__ res,
              float* __restrict__ C, int K, int lda, int ldb, int ldc,
              size_t aS, size_t bS, size_t cS, float alpha)
{
    extern __shared__ float sm[];   // 2 stages x (A 4096 + B 4096) floats = 64 KB
    const int tid  = threadIdx.x;
    const int w    = tid >> 5;
    const int lane = tid & 31;
    const int g    = lane >> 2;     // 0..7
    const int tig  = lane & 3;      // 0..3
    const int wm   = (w >> 2) * 64; // warp M offset in tile
    const int wn   = (w & 3) * 32;  // warp N offset in tile
    const size_t bm = (size_t)blockIdx.y * 128;
    const size_t bn = (size_t)blockIdx.x * 128;
    const float* Ap = A + aS * blockIdx.z;
    const float* Bp = B + bS * blockIdx.z;

    float acc[4][4][4];
    #pragma unroll
    for (int i = 0; i < 4; i++)
        #pragma unroll
        for (int j = 0; j < 4; j++)
            #pragma unroll
            for (int t = 0; t < 4; t++) acc[i][j][t] = 0.f;

    float* Ast[2] = { sm,        sm + 8192 };
    float* Bst[2] = { sm + 4096, sm + 8192 + 4096 };

    // per-thread load slots: 4 float4 per tile (A and B)
    const int nch = K >> 5;

    // ---- prologue: stage 0 ----
    {
        #pragma unroll
        for (int i = 0; i < 4; i++) {
            const int fidx = i * 256 + tid;       // 0..1023
            const int r  = fidx >> 3;
            const int c4 = fidx & 7;
            const int so = r * 32 + ((c4 ^ (r & 7)) << 2);
            CP_ASYNC16(smem_u32(Ast[0] + so), Ap + (bm + r) * (size_t)lda + (c4 << 2));
            CP_ASYNC16(smem_u32(Bst[0] + so), Bp + (bn + r) * (size_t)ldb + (c4 << 2));
        }
        CP_COMMIT();
    }

    for (int c = 0; c < nch; c++) {
        const int st = c & 1;
        if (c + 1 < nch) {
            const int k0 = (c + 1) << 5;
            float* An = Ast[st ^ 1];
            float* Bn = Bst[st ^ 1];
            #pragma unroll
            for (int i = 0; i < 4; i++) {
                const int fidx = i * 256 + tid;
                const int r  = fidx >> 3;
                const int c4 = fidx & 7;
                const int so = r * 32 + ((c4 ^ (r & 7)) << 2);
                CP_ASYNC16(smem_u32(An + so), Ap + (bm + r) * (size_t)lda + k0 + (c4 << 2));
                CP_ASYNC16(smem_u32(Bn + so), Bp + (bn + r) * (size_t)ldb + k0 + (c4 << 2));
            }
            CP_COMMIT();
            CP_WAIT(1);
        } else {
            CP_WAIT(0);
        }
        __syncthreads();

        const float* Asm = Ast[st];
        const float* Bsm = Bst[st];
        #pragma unroll
        for (int s = 0; s < 4; s++) {
            uint32_t af[4][4];
            uint32_t bf[4][2];
            const int cc = s * 8 + tig;
            #pragma unroll
            for (int mt = 0; mt < 4; mt++) {
                const int r = wm + mt * 16 + g;
                af[mt][0] = __float_as_uint(Asm[sw_addr(r,     cc)]);
                af[mt][1] = __float_as_uint(Asm[sw_addr(r + 8, cc)]);
                af[mt][2] = __float_as_uint(Asm[sw_addr(r,     cc + 4)]);
                af[mt][3] = __float_as_uint(Asm[sw_addr(r + 8, cc + 4)]);
            }
            #pragma unroll
            for (int nt = 0; nt < 4; nt++) {
                const int n = wn + nt * 8 + g;
                bf[nt][0] = __float_as_uint(Bsm[sw_addr(n, cc)]);
                bf[nt][1] = __float_as_uint(Bsm[sw_addr(n, cc + 4)]);
            }
            #pragma unroll
            for (int mt = 0; mt < 4; mt++)
                #pragma unroll
                for (int nt = 0; nt < 4; nt++)
                    MMA_TF32(acc[mt][nt], af[mt], bf[nt]);
        }
        __syncthreads();
    }

    // ---- epilogue ----
    float* Cb = C + cS * blockIdx.z;
    const float* Rb = res ? res + cS * blockIdx.z : (const float*)0;
    #pragma unroll
    for (int mt = 0; mt < 4; mt++) {
        #pragma unroll
        for (int nt = 0; nt < 4; nt++) {
            const size_t row0 = bm + wm + mt * 16 + g;
            const int    col  = (int)bn + wn + nt * 8 + tig * 2;
            float b0 = 0.f, b1 = 0.f;
            if (bias) { b0 = bias[col]; b1 = bias[col + 1]; }
            // rows row0 and row0+8
            #pragma unroll
            for (int h = 0; h < 2; h++) {
                const size_t r = row0 + h * 8;
                float v0 = acc[mt][nt][h * 2 + 0] * alpha + b0;
                float v1 = acc[mt][nt][h * 2 + 1] * alpha + b1;
                if (RELU) { v0 = fmaxf(v0, 0.f); v1 = fmaxf(v1, 0.f); }
                if (Rb) {
                    v0 += Rb[r * (size_t)ldc + col];
                    v1 += Rb[r * (size_t)ldc + col + 1];
                }
                float2 o = make_float2(v0, v1);
                *(float2*)(Cb + r * (size_t)ldc + col) = o;
            }
        }
    }
}

// ================= transpose: out[C,R] = in[R,C]^T (batched) =================
__global__ void transpose_k(const float* __restrict__ in, float* __restrict__ out,
                            int rows, int cols, size_t inS, size_t outS)
{
    __shared__ float t[32][33];
    const float* I = in + inS * blockIdx.z;
    float* O = out + outS * blockIdx.z;
    const int c0 = blockIdx.x * 32, r0 = blockIdx.y * 32;
    const int tx = threadIdx.x & 31, ty = threadIdx.x >> 5;   // 256 thr = 32x8
    #pragma unroll
    for (int i = ty; i < 32; i += 8)
        t[i][tx] = I[(size_t)(r0 + i) * cols + c0 + tx];
    __syncthreads();
    #pragma unroll
    for (int i = ty; i < 32; i += 8)
        O[(size_t)(c0 + i) * rows + r0 + tx] = t[tx][i];
}

// ---------------- block reductions (256 threads) ----------------
__device__ __forceinline__ float blockSum(float v) {
    __shared__ float red[8];
    #pragma unroll
    for (int o = 16; o > 0; o >>= 1) v += __shfl_xor_sync(0xffffffffu, v, o);
    __syncthreads();
    if ((threadIdx.x & 31) == 0) red[threadIdx.x >> 5] = v;
    __syncthreads();
    float r = red[0];
    #pragma unroll
    for (int i = 1; i < 8; i++) r += red[i];
    return r;
}
__device__ __forceinline__ float blockMax(float v) {
    __shared__ float redm[8];
    #pragma unroll
    for (int o = 16; o > 0; o >>= 1) v = fmaxf(v, __shfl_xor_sync(0xffffffffu, v, o));
    __syncthreads();
    if ((threadIdx.x & 31) == 0) redm[threadIdx.x >> 5] = v;
    __syncthreads();
    float r = redm[0];
    #pragma unroll
    for (int i = 1; i < 8; i++) r = fmaxf(r, redm[i]);
    return r;
}

// ---------------- LayerNorm (faithful to buggy reference) ----------------
__global__ void ln_kernel(const float* __restrict__ x, const float* __restrict__ g,
                          const float* __restrict__ b, float* __restrict__ out) {
    size_t row = blockIdx.x;
    const float* xr = x + row * Dm;
    int tid = threadIdx.x;
    float v0 = xr[tid], v1 = xr[tid + 256], v2 = xr[tid + 512];
    float mu = blockSum(v0 + v1 + v2) * (1.0f / Dm);
    float d0 = v0 - mu, d1 = v1 - mu, d2 = v2 - mu;
    float var = blockSum(d0 * d0 + d1 * d1 + d2 * d2) * (1.0f / (Dm - 1));
    float c = mu / sqrtf(var);           // reference's bug, reproduced exactly
    float* orow = out + row * Dm;
    orow[tid]       = (v0 - c) * g[tid]       + b[tid];
    orow[tid + 256] = (v1 - c) * g[tid + 256] + b[tid + 256];
    orow[tid + 512] = (v2 - c) * g[tid + 512] + b[tid + 512];
}

// ---------------- row softmax over 4096 ----------------
__global__ void softmax_kernel(float* __restrict__ S) {
    size_t row = blockIdx.x;
    float* sr = S + row * (size_t)Tt;
    int tid = threadIdx.x;
    float v[16];
    float m = -1e30f;
    #pragma unroll
    for (int i = 0; i < 16; i++) { v[i] = sr[tid + i * 256]; m = fmaxf(m, v[i]); }
    m = blockMax(m);
    float s = 0.f;
    #pragma unroll
    for (int i = 0; i < 16; i++) { v[i] = __expf(v[i] - m); s += v[i]; }
    s = blockSum(s);
    float inv = 1.0f / s;
    #pragma unroll
    for (int i = 0; i < 16; i++) sr[tid + i * 256] = v[i] * inv;
}

// ---------------- launch ----------------
extern "C" void kernel_launch(void* const* d_in, const int* in_sizes, int n_in,
                              void* d_out, int out_size) {
    const float* x     = (const float*)d_in[0];
    const float* ln1_g = (const float*)d_in[1];
    const float* ln1_b = (const float*)d_in[2];
    const float* wq    = (const float*)d_in[3];
    const float* wk    = (const float*)d_in[4];
    const float* wv    = (const float*)d_in[5];
    const float* ln2_g = (const float*)d_in[6];
    const float* ln2_b = (const float*)d_in[7];
    const float* fc1_w = (const float*)d_in[8];
    const float* fc1_b = (const float*)d_in[9];
    const float* fc2_w = (const float*)d_in[10];
    const float* fc2_b = (const float*)d_in[11];
    float* out = (float*)d_out;

    float *y, *q, *k, *v, *att, *h, *wt, *s;
    cudaGetSymbolAddress((void**)&y,   g_y);
    cudaGetSymbolAddress((void**)&q,   g_q);
    cudaGetSymbolAddress((void**)&k,   g_k);
    cudaGetSymbolAddress((void**)&v,   g_v);
    cudaGetSymbolAddress((void**)&att, g_att);
    cudaGetSymbolAddress((void**)&h,   g_h);
    cudaGetSymbolAddress((void**)&wt,  g_wt);
    cudaGetSymbolAddress((void**)&s,   g_s);
    float* wqT = wt;
    float* wkT = wt + (size_t)Dm * Dm;
    float* wvT = wt + 2 * (size_t)Dm * Dm;
    float* vT  = h;   // h is free until fc1

    const size_t sTD = (size_t)Tt * Dm;
    const size_t sTT = (size_t)Tt * Tt;
    const float scale = 1.0f / sqrtf((float)Dm);
    const int SMEM = 64 * 1024;

    static int attr_done = 0;
    if (!attr_done) {
        cudaFuncSetAttribute(gemm_mma<false>, cudaFuncAttributeMaxDynamicSharedMemorySize, SMEM);
        cudaFuncSetAttribute(gemm_mma<true>,  cudaFuncAttributeMaxDynamicSharedMemorySize, SMEM);
        attr_done = 1;
    }

    // 0. transpose QKV weights ([K,N] -> [N,K]) so every GEMM is NT
    dim3 gtw(Dm / 32, Dm / 32, 1);
    transpose_k<<<gtw, 256>>>(wq, wqT, Dm, Dm, 0, 0);
    transpose_k<<<gtw, 256>>>(wk, wkT, Dm, Dm, 0, 0);
    transpose_k<<<gtw, 256>>>(wv, wvT, Dm, Dm, 0, 0);

    // 1. LN1
    ln_kernel<<<MTOT, 256>>>(x, ln1_g, ln1_b, y);

    // 2. Q,K,V projections: [16384,768] @ [768,768]^T
    dim3 gproj(Dm / 128, MTOT / 128, 1);
    gemm_mma<false><<<gproj, 256, SMEM>>>(y, wqT, 0, 0, q, Dm, Dm, Dm, Dm, 0, 0, 0, 1.0f);
    gemm_mma<false><<<gproj, 256, SMEM>>>(y, wkT, 0, 0, k, Dm, Dm, Dm, Dm, 0, 0, 0, 1.0f);
    gemm_mma<false><<<gproj, 256, SMEM>>>(y, wvT, 0, 0, v, Dm, Dm, Dm, Dm, 0, 0, 0, 1.0f);

    // 2b. transpose V per batch: [T,D] -> [D,T]
    dim3 gtv(Dm / 32, Tt / 32, NB);
    transpose_k<<<gtv, 256>>>(v, vT, Tt, Dm, sTD, sTD);

    // 3. scores = scale * Q @ K^T  (K already [N=T, K=D])
    dim3 gsc(Tt / 128, Tt / 128, NB);
    gemm_mma<false><<<gsc, 256, SMEM>>>(q, k, 0, 0, s, Dm, Dm, Dm, Tt, sTD, sTD, sTT, scale);

    // 4. softmax rows
    softmax_kernel<<<NB * Tt, 256>>>(s);

    // 5. att = A @ V = A @ (V^T)^T  (NT with B = vT [D, T])
    dim3 gav(Dm / 128, Tt / 128, NB);
    gemm_mma<false><<<gav, 256, SMEM>>>(s, vT, 0, 0, att, Tt, Tt, Tt, Dm, sTT, sTD, sTD, 1.0f);

    // 6. LN2
    ln_kernel<<<MTOT, 256>>>(att, ln2_g, ln2_b, y);

    // 7. MLP fc1 (+bias, ReLU): fc1_w is [O,D] = NT already
    gemm_mma<true><<<gproj, 256, SMEM>>>(y, fc1_w, fc1_b, 0, h, Dm, Dm, Dm, Dm, 0, 0, 0, 1.0f);

    // 8. MLP fc2 (+bias, +residual x) -> out
    gemm_mma<false><<<gproj, 256, SMEM>>>(h, fc2_w, fc2_b, x, out, Dm, Dm, Dm, Dm, 0, 0, 0, 1.0f);
}

// round 5
// speedup vs baseline: 4.1284x; 2.0275x over previous
#include <cuda_runtime.h>
#include <cuda_bf16.h>
#include <cstdint>
#include <math.h>

#define Dm   768
#define Tt   4096
#define NB   4
#define MTOT (NB * Tt)   // 16384

typedef __nv_bfloat16 bf16;

// ---------------- scratch (static __device__ — no allocations) ----------------
__device__ float g_s  [(size_t)NB * Tt * Tt];   // 256 MB fp32 scores
__device__ float g_att[MTOT * Dm];              // fp32 attention out
__device__ bf16  g_p  [(size_t)NB * Tt * Tt];   // 128 MB bf16 probabilities
__device__ bf16  g_yb [MTOT * Dm];              // LN out (bf16), reused LN1/LN2
__device__ bf16  g_qb [MTOT * Dm];
__device__ bf16  g_kb [MTOT * Dm];
__device__ bf16  g_vt [MTOT * Dm];              // vT: [Dm, MTOT]
__device__ bf16  g_hb [MTOT * Dm];
__device__ bf16  g_wb [5 * Dm * Dm];            // wqT, wkT, wvT, fc1w, fc2w (bf16)

// ================= helpers =================
__device__ __forceinline__ uint32_t smem_u32(const void* p) {
    uint32_t a;
    asm("{ .reg .u64 t; cvta.to.shared.u64 t, %1; cvt.u32.u64 %0, t; }" : "=r"(a) : "l"(p));
    return a;
}

#define CP_ASYNC16(dst, src) \
    asm volatile("cp.async.cg.shared.global [%0], [%1], 16;" :: "r"(dst), "l"(src))
#define CP_COMMIT() asm volatile("cp.async.commit_group;" ::: "memory")
#define CP_WAIT(n)  asm volatile("cp.async.wait_group %0;" :: "n"(n) : "memory")

#define MMA_BF16(d, a, b) \
    asm volatile("mma.sync.aligned.m16n8k16.row.col.f32.bf16.bf16.f32 " \
        "{%0,%1,%2,%3}, {%4,%5,%6,%7}, {%8,%9}, {%0,%1,%2,%3};" \
        : "+f"((d)[0]), "+f"((d)[1]), "+f"((d)[2]), "+f"((d)[3]) \
        : "r"((a)[0]), "r"((a)[1]), "r"((a)[2]), "r"((a)[3]), \
          "r"((b)[0]), "r"((b)[1]))

// swizzled BYTE offset inside a [128 rows x 128 bytes] tile
__device__ __forceinline__ int swb(int r, int cb) {
    return (r * 128 + cb) ^ ((r & 7) << 4);
}

// ================= bf16 mma.sync GEMM =================
// NT: C[M,N] = alpha * A[M,K] @ B[N,K]^T  (+bias)(relu)(+res)
// 256 threads, CTA tile 128x128, warp tile 64x32, K-chunk 64 (bf16), 2-stage cp.async.
template <bool OUTB, bool RELU>
__global__ __launch_bounds__(256)
void gemm_bf16(const bf16* __restrict__ A, const bf16* __restrict__ B,
               const float* __restrict__ bias, const float* __restrict__ res,
               void* __restrict__ Cv, int K, int lda, int ldb, int ldc,
               size_t aS, size_t bS, size_t cS, float alpha)
{
    extern __shared__ char sm[];    // 2 stages x (A 16KB + B 16KB) = 64 KB
    const int tid  = threadIdx.x;
    const int w    = tid >> 5;
    const int lane = tid & 31;
    const int g    = lane >> 2;
    const int tig  = lane & 3;
    const int wm   = (w >> 2) * 64;
    const int wn   = (w & 3) * 32;
    const size_t bm = (size_t)blockIdx.y * 128;
    const size_t bn = (size_t)blockIdx.x * 128;
    const bf16* Ap = A + aS * blockIdx.z;
    const bf16* Bp = B + bS * blockIdx.z;

    float acc[4][4][4];
    #pragma unroll
    for (int i = 0; i < 4; i++)
        #pragma unroll
        for (int j = 0; j < 4; j++)
            #pragma unroll
            for (int t = 0; t < 4; t++) acc[i][j][t] = 0.f;

    char* Ast[2] = { sm,         sm + 32768 };
    char* Bst[2] = { sm + 16384, sm + 32768 + 16384 };
    const int nch = K >> 6;

    // ---- prologue: stage 0 ----
    #pragma unroll
    for (int i = 0; i < 4; i++) {
        const int fidx = i * 256 + tid;       // 0..1023 chunks of 16B
        const int r  = fidx >> 3;
        const int c4 = fidx & 7;
        const int dst = r * 128 + ((c4 ^ (r & 7)) << 4);
        CP_ASYNC16(smem_u32(Ast[0] + dst), Ap + (bm + r) * (size_t)lda + c4 * 8);
        CP_ASYNC16(smem_u32(Bst[0] + dst), Bp + (bn + r) * (size_t)ldb + c4 * 8);
    }
    CP_COMMIT();

    for (int c = 0; c < nch; c++) {
        const int st = c & 1;
        if (c + 1 < nch) {
            const int k0 = (c + 1) << 6;
            char* An = Ast[st ^ 1];
            char* Bn = Bst[st ^ 1];
            #pragma unroll
            for (int i = 0; i < 4; i++) {
                const int fidx = i * 256 + tid;
                const int r  = fidx >> 3;
                const int c4 = fidx & 7;
                const int dst = r * 128 + ((c4 ^ (r & 7)) << 4);
                CP_ASYNC16(smem_u32(An + dst), Ap + (bm + r) * (size_t)lda + k0 + c4 * 8);
                CP_ASYNC16(smem_u32(Bn + dst), Bp + (bn + r) * (size_t)ldb + k0 + c4 * 8);
            }
            CP_COMMIT();
            CP_WAIT(1);
        } else {
            CP_WAIT(0);
        }
        __syncthreads();

        const char* Asm = Ast[st];
        const char* Bsm = Bst[st];
        #pragma unroll
        for (int ks = 0; ks < 4; ks++) {      // 4 x k16 steps per 64-K chunk
            const int cb0 = ks * 32 + 4 * tig;
            const int cb1 = cb0 + 16;
            uint32_t af[4][4];
            uint32_t bfr[4][2];
            #pragma unroll
            for (int mt = 0; mt < 4; mt++) {
                const int r = wm + mt * 16 + g;
                af[mt][0] = *(const uint32_t*)(Asm + swb(r,     cb0));
                af[mt][1] = *(const uint32_t*)(Asm + swb(r + 8, cb0));
                af[mt][2] = *(const uint32_t*)(Asm + swb(r,     cb1));
                af[mt][3] = *(const uint32_t*)(Asm + swb(r + 8, cb1));
            }
            #pragma unroll
            for (int nt = 0; nt < 4; nt++) {
                const int n = wn + nt * 8 + g;
                bfr[nt][0] = *(const uint32_t*)(Bsm + swb(n, cb0));
                bfr[nt][1] = *(const uint32_t*)(Bsm + swb(n, cb1));
            }
            #pragma unroll
            for (int mt = 0; mt < 4; mt++)
                #pragma unroll
                for (int nt = 0; nt < 4; nt++)
                    MMA_BF16(acc[mt][nt], af[mt], bfr[nt]);
        }
        __syncthreads();
    }

    // ---- epilogue ----
    float* Cf = (float*)Cv + cS * blockIdx.z;
    bf16*  Cb = (bf16*)Cv  + cS * blockIdx.z;
    const float* Rb = res ? res + cS * blockIdx.z : (const float*)0;
    #pragma unroll
    for (int mt = 0; mt < 4; mt++) {
        #pragma unroll
        for (int nt = 0; nt < 4; nt++) {
            const size_t row0 = bm + wm + mt * 16 + g;
            const int    col  = (int)bn + wn + nt * 8 + tig * 2;
            float b0 = 0.f, b1 = 0.f;
            if (bias) { b0 = bias[col]; b1 = bias[col + 1]; }
            #pragma unroll
            for (int h = 0; h < 2; h++) {
                const size_t r = row0 + h * 8;
                float v0 = acc[mt][nt][h * 2 + 0] * alpha + b0;
                float v1 = acc[mt][nt][h * 2 + 1] * alpha + b1;
                if (RELU) { v0 = fmaxf(v0, 0.f); v1 = fmaxf(v1, 0.f); }
                if (Rb) {
                    v0 += Rb[r * (size_t)ldc + col];
                    v1 += Rb[r * (size_t)ldc + col + 1];
                }
                if (OUTB) {
                    __nv_bfloat162 o;
                    o.x = __float2bfloat16(v0);
                    o.y = __float2bfloat16(v1);
                    *(__nv_bfloat162*)(Cb + r * (size_t)ldc + col) = o;
                } else {
                    float2 o = make_float2(v0, v1);
                    *(float2*)(Cf + r * (size_t)ldc + col) = o;
                }
            }
        }
    }
}

// ================= transpose + convert fp32 -> bf16: out[C,R] = (bf16)in[R,C]^T =================
__global__ void transpose_cvt(const float* __restrict__ in, bf16* __restrict__ out,
                              int rows, int cols)
{
    __shared__ float t[32][33];
    const int c0 = blockIdx.x * 32, r0 = blockIdx.y * 32;
    const int tx = threadIdx.x & 31, ty = threadIdx.x >> 5;
    #pragma unroll
    for (int i = ty; i < 32; i += 8)
        t[i][tx] = in[(size_t)(r0 + i) * cols + c0 + tx];
    __syncthreads();
    #pragma unroll
    for (int i = ty; i < 32; i += 8)
        out[(size_t)(c0 + i) * rows + r0 + tx] = __float2bfloat16(t[tx][i]);
}

// ================= elementwise fp32 -> bf16 =================
__global__ void cvt_kernel(const float* __restrict__ in, bf16* __restrict__ out, int n) {
    int i = blockIdx.x * 256 + threadIdx.x;
    if (i < n) out[i] = __float2bfloat16(in[i]);
}

// ---------------- block reductions (256 threads) ----------------
__device__ __forceinline__ float blockSum(float v) {
    __shared__ float red[8];
    #pragma unroll
    for (int o = 16; o > 0; o >>= 1) v += __shfl_xor_sync(0xffffffffu, v, o);
    __syncthreads();
    if ((threadIdx.x & 31) == 0) red[threadIdx.x >> 5] = v;
    __syncthreads();
    float r = red[0];
    #pragma unroll
    for (int i = 1; i < 8; i++) r += red[i];
    return r;
}
__device__ __forceinline__ float blockMax(float v) {
    __shared__ float redm[8];
    #pragma unroll
    for (int o = 16; o > 0; o >>= 1) v = fmaxf(v, __shfl_xor_sync(0xffffffffu, v, o));
    __syncthreads();
    if ((threadIdx.x & 31) == 0) redm[threadIdx.x >> 5] = v;
    __syncthreads();
    float r = redm[0];
    #pragma unroll
    for (int i = 1; i < 8; i++) r = fmaxf(r, redm[i]);
    return r;
}

// ---------------- LayerNorm (faithful to buggy reference), bf16 out ----------------
__global__ void ln_kernel(const float* __restrict__ x, const float* __restrict__ g,
                          const float* __restrict__ b, bf16* __restrict__ out) {
    size_t row = blockIdx.x;
    const float* xr = x + row * Dm;
    int tid = threadIdx.x;
    float v0 = xr[tid], v1 = xr[tid + 256], v2 = xr[tid + 512];
    float mu = blockSum(v0 + v1 + v2) * (1.0f / Dm);
    float d0 = v0 - mu, d1 = v1 - mu, d2 = v2 - mu;
    float var = blockSum(d0 * d0 + d1 * d1 + d2 * d2) * (1.0f / (Dm - 1));
    float c = mu / sqrtf(var);           // reference's bug, reproduced exactly
    bf16* orow = out + row * Dm;
    orow[tid]       = __float2bfloat16((v0 - c) * g[tid]       + b[tid]);
    orow[tid + 256] = __float2bfloat16((v1 - c) * g[tid + 256] + b[tid + 256]);
    orow[tid + 512] = __float2bfloat16((v2 - c) * g[tid + 512] + b[tid + 512]);
}

// ---------------- row softmax over 4096: fp32 in, bf16 out ----------------
__global__ void softmax_kernel(const float* __restrict__ S, bf16* __restrict__ P) {
    size_t row = blockIdx.x;
    const float* sr = S + row * (size_t)Tt;
    bf16* pr = P + row * (size_t)Tt;
    int tid = threadIdx.x;
    float v[16];
    float m = -1e30f;
    #pragma unroll
    for (int i = 0; i < 16; i++) { v[i] = sr[tid + i * 256]; m = fmaxf(m, v[i]); }
    m = blockMax(m);
    float s = 0.f;
    #pragma unroll
    for (int i = 0; i < 16; i++) { v[i] = __expf(v[i] - m); s += v[i]; }
    s = blockSum(s);
    float inv = 1.0f / s;
    #pragma unroll
    for (int i = 0; i < 16; i++) pr[tid + i * 256] = __float2bfloat16(v[i] * inv);
}

// ---------------- launch ----------------
extern "C" void kernel_launch(void* const* d_in, const int* in_sizes, int n_in,
                              void* d_out, int out_size) {
    const float* x     = (const float*)d_in[0];
    const float* ln1_g = (const float*)d_in[1];
    const float* ln1_b = (const float*)d_in[2];
    const float* wq    = (const float*)d_in[3];
    const float* wk    = (const float*)d_in[4];
    const float* wv    = (const float*)d_in[5];
    const float* ln2_g = (const float*)d_in[6];
    const float* ln2_b = (const float*)d_in[7];
    const float* fc1_w = (const float*)d_in[8];
    const float* fc1_b = (const float*)d_in[9];
    const float* fc2_w = (const float*)d_in[10];
    const float* fc2_b = (const float*)d_in[11];
    float* out = (float*)d_out;

    float *s, *att;
    bf16 *p, *yb, *qb, *kb, *vt, *hb, *wb;
    cudaGetSymbolAddress((void**)&s,   g_s);
    cudaGetSymbolAddress((void**)&att, g_att);
    cudaGetSymbolAddress((void**)&p,   g_p);
    cudaGetSymbolAddress((void**)&yb,  g_yb);
    cudaGetSymbolAddress((void**)&qb,  g_qb);
    cudaGetSymbolAddress((void**)&kb,  g_kb);
    cudaGetSymbolAddress((void**)&vt,  g_vt);
    cudaGetSymbolAddress((void**)&hb,  g_hb);
    cudaGetSymbolAddress((void**)&wb,  g_wb);
    bf16* wqTb = wb;
    bf16* wkTb = wb + (size_t)Dm * Dm;
    bf16* wvTb = wb + 2 * (size_t)Dm * Dm;
    bf16* f1b  = wb + 3 * (size_t)Dm * Dm;
    bf16* f2b  = wb + 4 * (size_t)Dm * Dm;

    const size_t sTD = (size_t)Tt * Dm;
    const size_t sTT = (size_t)Tt * Tt;
    const float scale = 1.0f / sqrtf((float)Dm);
    const int SMEM = 64 * 1024;

    cudaFuncSetAttribute(gemm_bf16<true,  false>, cudaFuncAttributeMaxDynamicSharedMemorySize, SMEM);
    cudaFuncSetAttribute(gemm_bf16<false, false>, cudaFuncAttributeMaxDynamicSharedMemorySize, SMEM);
    cudaFuncSetAttribute(gemm_bf16<true,  true >, cudaFuncAttributeMaxDynamicSharedMemorySize, SMEM);

    // 0. weight prep: transpose+cvt QKV ([K,N]->[N,K] bf16); cvt fc1/fc2 ([O,D] bf16)
    dim3 gtw(Dm / 32, Dm / 32, 1);
    transpose_cvt<<<gtw, 256>>>(wq, wqTb, Dm, Dm);
    transpose_cvt<<<gtw, 256>>>(wk, wkTb, Dm, Dm);
    transpose_cvt<<<gtw, 256>>>(wv, wvTb, Dm, Dm);
    const int nW = Dm * Dm;
    cvt_kernel<<<(nW + 255) / 256, 256>>>(fc1_w, f1b, nW);
    cvt_kernel<<<(nW + 255) / 256, 256>>>(fc2_w, f2b, nW);

    // 1. LN1 -> yb (bf16)
    ln_kernel<<<MTOT, 256>>>(x, ln1_g, ln1_b, yb);

    // 2. Q, K projections: [16384,768] @ [768,768]^T -> bf16
    dim3 gproj(Dm / 128, MTOT / 128, 1);
    gemm_bf16<true, false><<<gproj, 256, SMEM>>>(yb, wqTb, 0, 0, qb, Dm, Dm, Dm, Dm, 0, 0, 0, 1.0f);
    gemm_bf16<true, false><<<gproj, 256, SMEM>>>(yb, wkTb, 0, 0, kb, Dm, Dm, Dm, Dm, 0, 0, 0, 1.0f);

    // 2b. vT = Wv^T @ Y^T directly: C[768, 16384] = wvTb[768,768] @ yb[16384,768]^T
    dim3 gvt(MTOT / 128, Dm / 128, 1);
    gemm_bf16<true, false><<<gvt, 256, SMEM>>>(wvTb, yb, 0, 0, vt, Dm, Dm, Dm, MTOT, 0, 0, 0, 1.0f);

    // 3. scores = scale * Q @ K^T -> fp32, per batch
    dim3 gsc(Tt / 128, Tt / 128, NB);
    gemm_bf16<false, false><<<gsc, 256, SMEM>>>(qb, kb, 0, 0, s, Dm, Dm, Dm, Tt, sTD, sTD, sTT, scale);

    // 4. softmax rows: fp32 -> bf16 probabilities
    softmax_kernel<<<NB * Tt, 256>>>(s, p);

    // 5. att = P @ V = P @ (vT)^T -> fp32  (B = vt rows [Dm], ldb = MTOT, batch offset Tt)
    dim3 gav(Dm / 128, Tt / 128, NB);
    gemm_bf16<false, false><<<gav, 256, SMEM>>>(p, vt, 0, 0, att, Tt, Tt, MTOT, Dm, sTT, (size_t)Tt, sTD, 1.0f);

    // 6. LN2 -> yb (bf16)
    ln_kernel<<<MTOT, 256>>>(att, ln2_g, ln2_b, yb);

    // 7. MLP fc1 (+bias, ReLU) -> bf16 h
    gemm_bf16<true, true><<<gproj, 256, SMEM>>>(yb, f1b, fc1_b, 0, hb, Dm, Dm, Dm, Dm, 0, 0, 0, 1.0f);

    // 8. MLP fc2 (+bias, +residual x) -> fp32 out
    gemm_bf16<false, false><<<gproj, 256, SMEM>>>(hb, f2b, fc2_b, x, out, Dm, Dm, Dm, Dm, 0, 0, 0, 1.0f);
}

// round 6
// speedup vs baseline: 5.9047x; 1.4303x over previous
#include <cuda_runtime.h>
#include <cuda_bf16.h>
#include <cstdint>
#include <math.h>

#define Dm   768
#define Tt   4096
#define NB   4
#define MTOT (NB * Tt)   // 16384

typedef __nv_bfloat16 bf16;

// ---------------- scratch (static __device__ — no allocations) ----------------
__device__ float g_s  [(size_t)NB * Tt * Tt];   // 256 MB fp32 scores
__device__ float g_att[MTOT * Dm];              // fp32 attention out
__device__ bf16  g_p  [(size_t)NB * Tt * Tt];   // 128 MB bf16 probabilities
__device__ bf16  g_yb [MTOT * Dm];              // LN out (bf16), reused LN1/LN2
__device__ bf16  g_qb [MTOT * Dm];
__device__ bf16  g_kb [MTOT * Dm];
__device__ bf16  g_vt [MTOT * Dm];              // vT: [Dm, MTOT]
__device__ bf16  g_hb [MTOT * Dm];
__device__ bf16  g_wb [5 * Dm * Dm];            // wqT, wkT, wvT, fc1w, fc2w (bf16)

// ================= helpers =================
__device__ __forceinline__ uint32_t smem_u32(const void* p) {
    uint32_t a;
    asm("{ .reg .u64 t; cvta.to.shared.u64 t, %1; cvt.u32.u64 %0, t; }" : "=r"(a) : "l"(p));
    return a;
}

#define CP_ASYNC16(dst, src) \
    asm volatile("cp.async.cg.shared.global [%0], [%1], 16;" :: "r"(dst), "l"(src))
#define CP_COMMIT() asm volatile("cp.async.commit_group;" ::: "memory")
#define CP_WAIT(n)  asm volatile("cp.async.wait_group %0;" :: "n"(n) : "memory")

#define MMA_BF16(d, a, b) \
    asm volatile("mma.sync.aligned.m16n8k16.row.col.f32.bf16.bf16.f32 " \
        "{%0,%1,%2,%3}, {%4,%5,%6,%7}, {%8,%9}, {%0,%1,%2,%3};" \
        : "+f"((d)[0]), "+f"((d)[1]), "+f"((d)[2]), "+f"((d)[3]) \
        : "r"((a)[0]), "r"((a)[1]), "r"((a)[2]), "r"((a)[3]), \
          "r"((b)[0]), "r"((b)[1]))

#define LDMX4(r0, r1, r2, r3, addr) \
    asm volatile("ldmatrix.sync.aligned.m8n8.x4.shared.b16 {%0,%1,%2,%3}, [%4];" \
        : "=r"(r0), "=r"(r1), "=r"(r2), "=r"(r3) : "r"(addr))

// swizzled BYTE offset inside a [128 rows x 128 bytes] tile
__device__ __forceinline__ int swb(int r, int cb) {
    return (r * 128 + cb) ^ ((r & 7) << 4);
}

// ================= bf16 mma.sync GEMM (ldmatrix fragments) =================
// NT: C[M,N] = alpha * A[M,K] @ B[N,K]^T  (+bias)(relu)(+res)
// 256 threads, CTA tile 128x128, warp tile 64x32, K-chunk 64 (bf16), 2-stage cp.async.
template <bool OUTB, bool RELU>
__global__ __launch_bounds__(256)
void gemm_bf16(const bf16* __restrict__ A, const bf16* __restrict__ B,
               const float* __restrict__ bias, const float* __restrict__ res,
               void* __restrict__ Cv, int K, int lda, int ldb, int ldc,
               size_t aS, size_t bS, size_t cS, float alpha)
{
    extern __shared__ char sm[];    // 2 stages x (A 16KB + B 16KB) = 64 KB
    const int tid  = threadIdx.x;
    const int w    = tid >> 5;
    const int lane = tid & 31;
    const int g    = lane >> 2;
    const int tig  = lane & 3;
    const int wm   = (w >> 2) * 64;
    const int wn   = (w & 3) * 32;
    const size_t bm = (size_t)blockIdx.y * 128;
    const size_t bn = (size_t)blockIdx.x * 128;
    const bf16* Ap = A + aS * blockIdx.z;
    const bf16* Bp = B + bS * blockIdx.z;

    // ldmatrix per-lane source coordinates
    const int lrA = (lane & 7) + ((lane >> 3) & 1) * 8;   // row within 16-row A block
    const int lcA = (lane >> 4) * 16;                     // 0 or 16 byte col
    const int lrB = (lane & 7) + ((lane >> 4) & 1) * 8;   // row within 16-row B block
    const int lcB = ((lane >> 3) & 1) * 16;

    float acc[4][4][4];
    #pragma unroll
    for (int i = 0; i < 4; i++)
        #pragma unroll
        for (int j = 0; j < 4; j++)
            #pragma unroll
            for (int t = 0; t < 4; t++) acc[i][j][t] = 0.f;

    char* Ast[2] = { sm,         sm + 32768 };
    char* Bst[2] = { sm + 16384, sm + 32768 + 16384 };
    const int nch = K >> 6;

    // ---- prologue: stage 0 ----
    #pragma unroll
    for (int i = 0; i < 4; i++) {
        const int fidx = i * 256 + tid;       // 0..1023 chunks of 16B
        const int r  = fidx >> 3;
        const int c4 = fidx & 7;
        const int dst = r * 128 + ((c4 ^ (r & 7)) << 4);
        CP_ASYNC16(smem_u32(Ast[0] + dst), Ap + (bm + r) * (size_t)lda + c4 * 8);
        CP_ASYNC16(smem_u32(Bst[0] + dst), Bp + (bn + r) * (size_t)ldb + c4 * 8);
    }
    CP_COMMIT();

    for (int c = 0; c < nch; c++) {
        const int st = c & 1;
        if (c + 1 < nch) {
            const int k0 = (c + 1) << 6;
            char* An = Ast[st ^ 1];
            char* Bn = Bst[st ^ 1];
            #pragma unroll
            for (int i = 0; i < 4; i++) {
                const int fidx = i * 256 + tid;
                const int r  = fidx >> 3;
                const int c4 = fidx & 7;
                const int dst = r * 128 + ((c4 ^ (r & 7)) << 4);
                CP_ASYNC16(smem_u32(An + dst), Ap + (bm + r) * (size_t)lda + k0 + c4 * 8);
                CP_ASYNC16(smem_u32(Bn + dst), Bp + (bn + r) * (size_t)ldb + k0 + c4 * 8);
            }
            CP_COMMIT();
            CP_WAIT(1);
        } else {
            CP_WAIT(0);
        }
        __syncthreads();

        const char* Asm = Ast[st];
        const char* Bsm = Bst[st];
        #pragma unroll
        for (int ks = 0; ks < 4; ks++) {      // 4 x k16 steps per 64-K chunk
            const int cb0 = ks * 32;
            uint32_t af[4][4];
            uint32_t bfr[4][2];
            #pragma unroll
            for (int mt = 0; mt < 4; mt++) {
                const uint32_t aadr = smem_u32(Asm + swb(wm + mt * 16 + lrA, cb0 + lcA));
                LDMX4(af[mt][0], af[mt][1], af[mt][2], af[mt][3], aadr);
            }
            #pragma unroll
            for (int np = 0; np < 2; np++) {  // pair of n8-tiles per ldmatrix.x4
                const uint32_t badr = smem_u32(Bsm + swb(wn + np * 16 + lrB, cb0 + lcB));
                LDMX4(bfr[np * 2][0], bfr[np * 2][1], bfr[np * 2 + 1][0], bfr[np * 2 + 1][1], badr);
            }
            #pragma unroll
            for (int mt = 0; mt < 4; mt++)
                #pragma unroll
                for (int nt = 0; nt < 4; nt++)
                    MMA_BF16(acc[mt][nt], af[mt], bfr[nt]);
        }
        __syncthreads();
    }

    // ---- epilogue ----
    float* Cf = (float*)Cv + cS * blockIdx.z;
    bf16*  Cb = (bf16*)Cv  + cS * blockIdx.z;
    const float* Rb = res ? res + cS * blockIdx.z : (const float*)0;
    #pragma unroll
    for (int mt = 0; mt < 4; mt++) {
        #pragma unroll
        for (int nt = 0; nt < 4; nt++) {
            const size_t row0 = bm + wm + mt * 16 + g;
            const int    col  = (int)bn + wn + nt * 8 + tig * 2;
            float b0 = 0.f, b1 = 0.f;
            if (bias) { b0 = bias[col]; b1 = bias[col + 1]; }
            #pragma unroll
            for (int h = 0; h < 2; h++) {
                const size_t r = row0 + h * 8;
                float v0 = acc[mt][nt][h * 2 + 0] * alpha + b0;
                float v1 = acc[mt][nt][h * 2 + 1] * alpha + b1;
                if (RELU) { v0 = fmaxf(v0, 0.f); v1 = fmaxf(v1, 0.f); }
                if (Rb) {
                    v0 += Rb[r * (size_t)ldc + col];
                    v1 += Rb[r * (size_t)ldc + col + 1];
                }
                if (OUTB) {
                    __nv_bfloat162 o;
                    o.x = __float2bfloat16(v0);
                    o.y = __float2bfloat16(v1);
                    *(__nv_bfloat162*)(Cb + r * (size_t)ldc + col) = o;
                } else {
                    float2 o = make_float2(v0, v1);
                    *(float2*)(Cf + r * (size_t)ldc + col) = o;
                }
            }
        }
    }
}

// ================= fused weight prep: 3x transpose+cvt, 2x cvt =================
// grid (24, 24, 5), block 256 (32x8)
__global__ void prep_weights(const float* __restrict__ wq, const float* __restrict__ wk,
                             const float* __restrict__ wv, const float* __restrict__ f1,
                             const float* __restrict__ f2, bf16* __restrict__ wb)
{
    const int z = blockIdx.z;
    const float* src = (z == 0) ? wq : (z == 1) ? wk : (z == 2) ? wv : (z == 3) ? f1 : f2;
    bf16* dst = wb + (size_t)z * Dm * Dm;
    const int c0 = blockIdx.x * 32, r0 = blockIdx.y * 32;
    const int tx = threadIdx.x & 31, ty = threadIdx.x >> 5;
    if (z < 3) {
        __shared__ float t[32][33];
        #pragma unroll
        for (int i = ty; i < 32; i += 8)
            t[i][tx] = src[(size_t)(r0 + i) * Dm + c0 + tx];
        __syncthreads();
        #pragma unroll
        for (int i = ty; i < 32; i += 8)
            dst[(size_t)(c0 + i) * Dm + r0 + tx] = __float2bfloat16(t[tx][i]);
    } else {
        #pragma unroll
        for (int i = ty; i < 32; i += 8)
            dst[(size_t)(r0 + i) * Dm + c0 + tx] = __float2bfloat16(src[(size_t)(r0 + i) * Dm + c0 + tx]);
    }
}

// ---------------- block reductions (256 threads) ----------------
__device__ __forceinline__ float blockSum(float v) {
    __shared__ float red[8];
    #pragma unroll
    for (int o = 16; o > 0; o >>= 1) v += __shfl_xor_sync(0xffffffffu, v, o);
    __syncthreads();
    if ((threadIdx.x & 31) == 0) red[threadIdx.x >> 5] = v;
    __syncthreads();
    float r = red[0];
    #pragma unroll
    for (int i = 1; i < 8; i++) r += red[i];
    return r;
}
__device__ __forceinline__ float blockMax(float v) {
    __shared__ float redm[8];
    #pragma unroll
    for (int o = 16; o > 0; o >>= 1) v = fmaxf(v, __shfl_xor_sync(0xffffffffu, v, o));
    __syncthreads();
    if ((threadIdx.x & 31) == 0) redm[threadIdx.x >> 5] = v;
    __syncthreads();
    float r = redm[0];
    #pragma unroll
    for (int i = 1; i < 8; i++) r = fmaxf(r, redm[i]);
    return r;
}

// ---------------- LayerNorm (faithful to buggy reference), bf16 out ----------------
__global__ void ln_kernel(const float* __restrict__ x, const float* __restrict__ g,
                          const float* __restrict__ b, bf16* __restrict__ out) {
    size_t row = blockIdx.x;
    const float* xr = x + row * Dm;
    int tid = threadIdx.x;
    float v0 = xr[tid], v1 = xr[tid + 256], v2 = xr[tid + 512];
    float mu = blockSum(v0 + v1 + v2) * (1.0f / Dm);
    float d0 = v0 - mu, d1 = v1 - mu, d2 = v2 - mu;
    float var = blockSum(d0 * d0 + d1 * d1 + d2 * d2) * (1.0f / (Dm - 1));
    float c = mu / sqrtf(var);           // reference's bug, reproduced exactly
    bf16* orow = out + row * Dm;
    orow[tid]       = __float2bfloat16((v0 - c) * g[tid]       + b[tid]);
    orow[tid + 256] = __float2bfloat16((v1 - c) * g[tid + 256] + b[tid + 256]);
    orow[tid + 512] = __float2bfloat16((v2 - c) * g[tid + 512] + b[tid + 512]);
}

// ---------------- row softmax over 4096: fp32 in, bf16 out ----------------
__global__ void softmax_kernel(const float* __restrict__ S, bf16* __restrict__ P) {
    size_t row = blockIdx.x;
    const float* sr = S + row * (size_t)Tt;
    bf16* pr = P + row * (size_t)Tt;
    int tid = threadIdx.x;
    float v[16];
    float m = -1e30f;
    #pragma unroll
    for (int i = 0; i < 16; i++) { v[i] = sr[tid + i * 256]; m = fmaxf(m, v[i]); }
    m = blockMax(m);
    float s = 0.f;
    #pragma unroll
    for (int i = 0; i < 16; i++) { v[i] = __expf(v[i] - m); s += v[i]; }
    s = blockSum(s);
    float inv = 1.0f / s;
    #pragma unroll
    for (int i = 0; i < 16; i++) pr[tid + i * 256] = __float2bfloat16(v[i] * inv);
}

// ---------------- launch ----------------
extern "C" void kernel_launch(void* const* d_in, const int* in_sizes, int n_in,
                              void* d_out, int out_size) {
    const float* x     = (const float*)d_in[0];
    const float* ln1_g = (const float*)d_in[1];
    const float* ln1_b = (const float*)d_in[2];
    const float* wq    = (const float*)d_in[3];
    const float* wk    = (const float*)d_in[4];
    const float* wv    = (const float*)d_in[5];
    const float* ln2_g = (const float*)d_in[6];
    const float* ln2_b = (const float*)d_in[7];
    const float* fc1_w = (const float*)d_in[8];
    const float* fc1_b = (const float*)d_in[9];
    const float* fc2_w = (const float*)d_in[10];
    const float* fc2_b = (const float*)d_in[11];
    float* out = (float*)d_out;

    float *s, *att;
    bf16 *p, *yb, *qb, *kb, *vt, *hb, *wb;
    cudaGetSymbolAddress((void**)&s,   g_s);
    cudaGetSymbolAddress((void**)&att, g_att);
    cudaGetSymbolAddress((void**)&p,   g_p);
    cudaGetSymbolAddress((void**)&yb,  g_yb);
    cudaGetSymbolAddress((void**)&qb,  g_qb);
    cudaGetSymbolAddress((void**)&kb,  g_kb);
    cudaGetSymbolAddress((void**)&vt,  g_vt);
    cudaGetSymbolAddress((void**)&hb,  g_hb);
    cudaGetSymbolAddress((void**)&wb,  g_wb);
    bf16* wqTb = wb;
    bf16* wkTb = wb + (size_t)Dm * Dm;
    bf16* wvTb = wb + 2 * (size_t)Dm * Dm;
    bf16* f1b  = wb + 3 * (size_t)Dm * Dm;
    bf16* f2b  = wb + 4 * (size_t)Dm * Dm;

    const size_t sTD = (size_t)Tt * Dm;
    const size_t sTT = (size_t)Tt * Tt;
    const float scale = 1.0f / sqrtf((float)Dm);
    const int SMEM = 64 * 1024;

    cudaFuncSetAttribute(gemm_bf16<true,  false>, cudaFuncAttributeMaxDynamicSharedMemorySize, SMEM);
    cudaFuncSetAttribute(gemm_bf16<false, false>, cudaFuncAttributeMaxDynamicSharedMemorySize, SMEM);
    cudaFuncSetAttribute(gemm_bf16<true,  true >, cudaFuncAttributeMaxDynamicSharedMemorySize, SMEM);

    // 0. fused weight prep (1 launch)
    dim3 gprep(Dm / 32, Dm / 32, 5);
    prep_weights<<<gprep, 256>>>(wq, wk, wv, fc1_w, fc2_w, wb);

    // 1. LN1 -> yb (bf16)
    ln_kernel<<<MTOT, 256>>>(x, ln1_g, ln1_b, yb);

    // 2. Q, K projections: [16384,768] @ [768,768]^T -> bf16
    dim3 gproj(Dm / 128, MTOT / 128, 1);
    gemm_bf16<true, false><<<gproj, 256, SMEM>>>(yb, wqTb, 0, 0, qb, Dm, Dm, Dm, Dm, 0, 0, 0, 1.0f);
    gemm_bf16<true, false><<<gproj, 256, SMEM>>>(yb, wkTb, 0, 0, kb, Dm, Dm, Dm, Dm, 0, 0, 0, 1.0f);

    // 2b. vT = Wv^T @ Y^T directly: C[768, 16384] = wvTb[768,768] @ yb[16384,768]^T
    dim3 gvt(MTOT / 128, Dm / 128, 1);
    gemm_bf16<true, false><<<gvt, 256, SMEM>>>(wvTb, yb, 0, 0, vt, Dm, Dm, Dm, MTOT, 0, 0, 0, 1.0f);

    // 3. scores = scale * Q @ K^T -> fp32, per batch
    dim3 gsc(Tt / 128, Tt / 128, NB);
    gemm_bf16<false, false><<<gsc, 256, SMEM>>>(qb, kb, 0, 0, s, Dm, Dm, Dm, Tt, sTD, sTD, sTT, scale);

    // 4. softmax rows: fp32 -> bf16 probabilities
    softmax_kernel<<<NB * Tt, 256>>>(s, p);

    // 5. att = P @ V = P @ (vT)^T -> fp32  (B = vt rows [Dm], ldb = MTOT, batch offset Tt)
    dim3 gav(Dm / 128, Tt / 128, NB);
    gemm_bf16<false, false><<<gav, 256, SMEM>>>(p, vt, 0, 0, att, Tt, Tt, MTOT, Dm, sTT, (size_t)Tt, sTD, 1.0f);

    // 6. LN2 -> yb (bf16)
    ln_kernel<<<MTOT, 256>>>(att, ln2_g, ln2_b, yb);

    // 7. MLP fc1 (+bias, ReLU) -> bf16 h
    gemm_bf16<true, true><<<gproj, 256, SMEM>>>(yb, f1b, fc1_b, 0, hb, Dm, Dm, Dm, Dm, 0, 0, 0, 1.0f);

    // 8. MLP fc2 (+bias, +residual x) -> fp32 out
    gemm_bf16<false, false><<<gproj, 256, SMEM>>>(hb, f2b, fc2_b, x, out, Dm, Dm, Dm, Dm, 0, 0, 0, 1.0f);
}

// round 7
// speedup vs baseline: 7.0306x; 1.1907x over previous
#include <cuda_runtime.h>
#include <cuda_bf16.h>
#include <cstdint>
#include <math.h>

#define Dm   768
#define Tt   4096
#define NB   4
#define MTOT (NB * Tt)   // 16384

typedef __nv_bfloat16 bf16;

// ---------------- scratch (static __device__ — no allocations) ----------------
__device__ float g_s  [(size_t)NB * Tt * Tt];   // 256 MB fp32 scores
__device__ float g_att[MTOT * Dm];              // fp32 attention out
__device__ bf16  g_p  [(size_t)NB * Tt * Tt];   // 128 MB bf16 probabilities
__device__ bf16  g_yb [MTOT * Dm];              // LN out (bf16), reused LN1/LN2
__device__ bf16  g_qb [MTOT * Dm];
__device__ bf16  g_kb [MTOT * Dm];
__device__ bf16  g_vt [MTOT * Dm];              // vT: [Dm, MTOT]
__device__ bf16  g_hb [MTOT * Dm];
__device__ bf16  g_wb [5 * Dm * Dm];            // wqT, wkT, wvT, fc1w, fc2w (bf16)

// ================= helpers =================
__device__ __forceinline__ uint32_t smem_u32(const void* p) {
    uint32_t a;
    asm("{ .reg .u64 t; cvta.to.shared.u64 t, %1; cvt.u32.u64 %0, t; }" : "=r"(a) : "l"(p));
    return a;
}

#define CP_ASYNC16(dst, src) \
    asm volatile("cp.async.cg.shared.global [%0], [%1], 16;" :: "r"(dst), "l"(src))
#define CP_COMMIT() asm volatile("cp.async.commit_group;" ::: "memory")
#define CP_WAIT(n)  asm volatile("cp.async.wait_group %0;" :: "n"(n) : "memory")

#define MMA_BF16(d, a, b) \
    asm volatile("mma.sync.aligned.m16n8k16.row.col.f32.bf16.bf16.f32 " \
        "{%0,%1,%2,%3}, {%4,%5,%6,%7}, {%8,%9}, {%0,%1,%2,%3};" \
        : "+f"((d)[0]), "+f"((d)[1]), "+f"((d)[2]), "+f"((d)[3]) \
        : "r"((a)[0]), "r"((a)[1]), "r"((a)[2]), "r"((a)[3]), \
          "r"((b)[0]), "r"((b)[1]))

#define LDMX4(r0, r1, r2, r3, addr) \
    asm volatile("ldmatrix.sync.aligned.m8n8.x4.shared.b16 {%0,%1,%2,%3}, [%4];" \
        : "=r"(r0), "=r"(r1), "=r"(r2), "=r"(r3) : "r"(addr))

// swizzled BYTE offset inside a [128 rows x 128 bytes] tile
__device__ __forceinline__ int swb(int r, int cb) {
    return (r * 128 + cb) ^ ((r & 7) << 4);
}

// ================= bf16 mma.sync GEMM (ldmatrix fragments) =================
// NT: C[M,N] = alpha * A[M,K] @ B[N,K]^T  (+bias)(relu)(+res)
// 256 threads, CTA tile 128x128, warp tile 64x32, K-chunk 64 (bf16), 2-stage cp.async.
// __launch_bounds__(256, 2): cap regs at 128 so 2 CTAs/SM co-reside (R6 limiter).
template <bool OUTB, bool RELU>
__global__ __launch_bounds__(256, 2)
void gemm_bf16(const bf16* __restrict__ A, const bf16* __restrict__ B,
               const float* __restrict__ bias, const float* __restrict__ res,
               void* __restrict__ Cv, int K, int lda, int ldb, int ldc,
               size_t aS, size_t bS, size_t cS, float alpha)
{
    extern __shared__ char sm[];    // 2 stages x (A 16KB + B 16KB) = 64 KB
    const int tid  = threadIdx.x;
    const int w    = tid >> 5;
    const int lane = tid & 31;
    const int g    = lane >> 2;
    const int tig  = lane & 3;
    const int wm   = (w >> 2) * 64;
    const int wn   = (w & 3) * 32;
    const size_t bm = (size_t)blockIdx.y * 128;
    const size_t bn = (size_t)blockIdx.x * 128;
    const bf16* Ap = A + aS * blockIdx.z;
    const bf16* Bp = B + bS * blockIdx.z;

    // ldmatrix per-lane source coordinates
    const int lrA = (lane & 7) + ((lane >> 3) & 1) * 8;   // row within 16-row A block
    const int lcA = (lane >> 4) * 16;                     // 0 or 16 byte col
    const int lrB = (lane & 7) + ((lane >> 4) & 1) * 8;   // row within 16-row B block
    const int lcB = ((lane >> 3) & 1) * 16;

    float acc[4][4][4];
    #pragma unroll
    for (int i = 0; i < 4; i++)
        #pragma unroll
        for (int j = 0; j < 4; j++)
            #pragma unroll
            for (int t = 0; t < 4; t++) acc[i][j][t] = 0.f;

    char* Ast[2] = { sm,         sm + 32768 };
    char* Bst[2] = { sm + 16384, sm + 32768 + 16384 };
    const int nch = K >> 6;

    // ---- prologue: stage 0 ----
    #pragma unroll
    for (int i = 0; i < 4; i++) {
        const int fidx = i * 256 + tid;       // 0..1023 chunks of 16B
        const int r  = fidx >> 3;
        const int c4 = fidx & 7;
        const int dst = r * 128 + ((c4 ^ (r & 7)) << 4);
        CP_ASYNC16(smem_u32(Ast[0] + dst), Ap + (bm + r) * (size_t)lda + c4 * 8);
        CP_ASYNC16(smem_u32(Bst[0] + dst), Bp + (bn + r) * (size_t)ldb + c4 * 8);
    }
    CP_COMMIT();

    for (int c = 0; c < nch; c++) {
        const int st = c & 1;
        if (c + 1 < nch) {
            const int k0 = (c + 1) << 6;
            char* An = Ast[st ^ 1];
            char* Bn = Bst[st ^ 1];
            #pragma unroll
            for (int i = 0; i < 4; i++) {
                const int fidx = i * 256 + tid;
                const int r  = fidx >> 3;
                const int c4 = fidx & 7;
                const int dst = r * 128 + ((c4 ^ (r & 7)) << 4);
                CP_ASYNC16(smem_u32(An + dst), Ap + (bm + r) * (size_t)lda + k0 + c4 * 8);
                CP_ASYNC16(smem_u32(Bn + dst), Bp + (bn + r) * (size_t)ldb + k0 + c4 * 8);
            }
            CP_COMMIT();
            CP_WAIT(1);
        } else {
            CP_WAIT(0);
        }
        __syncthreads();

        const char* Asm = Ast[st];
        const char* Bsm = Bst[st];
        #pragma unroll
        for (int ks = 0; ks < 4; ks++) {      // 4 x k16 steps per 64-K chunk
            const int cb0 = ks * 32;
            uint32_t af[4][4];
            uint32_t bfr[4][2];
            #pragma unroll
            for (int mt = 0; mt < 4; mt++) {
                const uint32_t aadr = smem_u32(Asm + swb(wm + mt * 16 + lrA, cb0 + lcA));
                LDMX4(af[mt][0], af[mt][1], af[mt][2], af[mt][3], aadr);
            }
            #pragma unroll
            for (int np = 0; np < 2; np++) {  // pair of n8-tiles per ldmatrix.x4
                const uint32_t badr = smem_u32(Bsm + swb(wn + np * 16 + lrB, cb0 + lcB));
                LDMX4(bfr[np * 2][0], bfr[np * 2][1], bfr[np * 2 + 1][0], bfr[np * 2 + 1][1], badr);
            }
            #pragma unroll
            for (int mt = 0; mt < 4; mt++)
                #pragma unroll
                for (int nt = 0; nt < 4; nt++)
                    MMA_BF16(acc[mt][nt], af[mt], bfr[nt]);
        }
        __syncthreads();
    }

    // ---- epilogue ----
    float* Cf = (float*)Cv + cS * blockIdx.z;
    bf16*  Cb = (bf16*)Cv  + cS * blockIdx.z;
    const float* Rb = res ? res + cS * blockIdx.z : (const float*)0;
    #pragma unroll
    for (int mt = 0; mt < 4; mt++) {
        #pragma unroll
        for (int nt = 0; nt < 4; nt++) {
            const size_t row0 = bm + wm + mt * 16 + g;
            const int    col  = (int)bn + wn + nt * 8 + tig * 2;
            float b0 = 0.f, b1 = 0.f;
            if (bias) { b0 = bias[col]; b1 = bias[col + 1]; }
            #pragma unroll
            for (int h = 0; h < 2; h++) {
                const size_t r = row0 + h * 8;
                float v0 = acc[mt][nt][h * 2 + 0] * alpha + b0;
                float v1 = acc[mt][nt][h * 2 + 1] * alpha + b1;
                if (RELU) { v0 = fmaxf(v0, 0.f); v1 = fmaxf(v1, 0.f); }
                if (Rb) {
                    v0 += Rb[r * (size_t)ldc + col];
                    v1 += Rb[r * (size_t)ldc + col + 1];
                }
                if (OUTB) {
                    __nv_bfloat162 o;
                    o.x = __float2bfloat16(v0);
                    o.y = __float2bfloat16(v1);
                    *(__nv_bfloat162*)(Cb + r * (size_t)ldc + col) = o;
                } else {
                    float2 o = make_float2(v0, v1);
                    *(float2*)(Cf + r * (size_t)ldc + col) = o;
                }
            }
        }
    }
}

// ================= fused weight prep: 3x transpose+cvt, 2x cvt =================
// grid (24, 24, 5), block 256 (32x8)
__global__ void prep_weights(const float* __restrict__ wq, const float* __restrict__ wk,
                             const float* __restrict__ wv, const float* __restrict__ f1,
                             const float* __restrict__ f2, bf16* __restrict__ wb)
{
    const int z = blockIdx.z;
    const float* src = (z == 0) ? wq : (z == 1) ? wk : (z == 2) ? wv : (z == 3) ? f1 : f2;
    bf16* dst = wb + (size_t)z * Dm * Dm;
    const int c0 = blockIdx.x * 32, r0 = blockIdx.y * 32;
    const int tx = threadIdx.x & 31, ty = threadIdx.x >> 5;
    if (z < 3) {
        __shared__ float t[32][33];
        #pragma unroll
        for (int i = ty; i < 32; i += 8)
            t[i][tx] = src[(size_t)(r0 + i) * Dm + c0 + tx];
        __syncthreads();
        #pragma unroll
        for (int i = ty; i < 32; i += 8)
            dst[(size_t)(c0 + i) * Dm + r0 + tx] = __float2bfloat16(t[tx][i]);
    } else {
        #pragma unroll
        for (int i = ty; i < 32; i += 8)
            dst[(size_t)(r0 + i) * Dm + c0 + tx] = __float2bfloat16(src[(size_t)(r0 + i) * Dm + c0 + tx]);
    }
}

// ---------------- block reductions (256 threads) ----------------
__device__ __forceinline__ float blockSum(float v) {
    __shared__ float red[8];
    #pragma unroll
    for (int o = 16; o > 0; o >>= 1) v += __shfl_xor_sync(0xffffffffu, v, o);
    __syncthreads();
    if ((threadIdx.x & 31) == 0) red[threadIdx.x >> 5] = v;
    __syncthreads();
    float r = red[0];
    #pragma unroll
    for (int i = 1; i < 8; i++) r += red[i];
    return r;
}
__device__ __forceinline__ float blockMax(float v) {
    __shared__ float redm[8];
    #pragma unroll
    for (int o = 16; o > 0; o >>= 1) v = fmaxf(v, __shfl_xor_sync(0xffffffffu, v, o));
    __syncthreads();
    if ((threadIdx.x & 31) == 0) redm[threadIdx.x >> 5] = v;
    __syncthreads();
    float r = redm[0];
    #pragma unroll
    for (int i = 1; i < 8; i++) r = fmaxf(r, redm[i]);
    return r;
}

// ---------------- LayerNorm (faithful to buggy reference), bf16 out ----------------
__global__ void ln_kernel(const float* __restrict__ x, const float* __restrict__ g,
                          const float* __restrict__ b, bf16* __restrict__ out) {
    size_t row = blockIdx.x;
    const float* xr = x + row * Dm;
    int tid = threadIdx.x;
    float v0 = xr[tid], v1 = xr[tid + 256], v2 = xr[tid + 512];
    float mu = blockSum(v0 + v1 + v2) * (1.0f / Dm);
    float d0 = v0 - mu, d1 = v1 - mu, d2 = v2 - mu;
    float var = blockSum(d0 * d0 + d1 * d1 + d2 * d2) * (1.0f / (Dm - 1));
    float c = mu / sqrtf(var);           // reference's bug, reproduced exactly
    bf16* orow = out + row * Dm;
    orow[tid]       = __float2bfloat16((v0 - c) * g[tid]       + b[tid]);
    orow[tid + 256] = __float2bfloat16((v1 - c) * g[tid + 256] + b[tid + 256]);
    orow[tid + 512] = __float2bfloat16((v2 - c) * g[tid + 512] + b[tid + 512]);
}

// ---------------- row softmax over 4096: fp32 in, bf16 out ----------------
__global__ void softmax_kernel(const float* __restrict__ S, bf16* __restrict__ P) {
    size_t row = blockIdx.x;
    const float* sr = S + row * (size_t)Tt;
    bf16* pr = P + row * (size_t)Tt;
    int tid = threadIdx.x;
    float v[16];
    float m = -1e30f;
    #pragma unroll
    for (int i = 0; i < 16; i++) { v[i] = sr[tid + i * 256]; m = fmaxf(m, v[i]); }
    m = blockMax(m);
    float s = 0.f;
    #pragma unroll
    for (int i = 0; i < 16; i++) { v[i] = __expf(v[i] - m); s += v[i]; }
    s = blockSum(s);
    float inv = 1.0f / s;
    #pragma unroll
    for (int i = 0; i < 16; i++) pr[tid + i * 256] = __float2bfloat16(v[i] * inv);
}

// ---------------- launch ----------------
extern "C" void kernel_launch(void* const* d_in, const int* in_sizes, int n_in,
                              void* d_out, int out_size) {
    const float* x     = (const float*)d_in[0];
    const float* ln1_g = (const float*)d_in[1];
    const float* ln1_b = (const float*)d_in[2];
    const float* wq    = (const float*)d_in[3];
    const float* wk    = (const float*)d_in[4];
    const float* wv    = (const float*)d_in[5];
    const float* ln2_g = (const float*)d_in[6];
    const float* ln2_b = (const float*)d_in[7];
    const float* fc1_w = (const float*)d_in[8];
    const float* fc1_b = (const float*)d_in[9];
    const float* fc2_w = (const float*)d_in[10];
    const float* fc2_b = (const float*)d_in[11];
    float* out = (float*)d_out;

    float *s, *att;
    bf16 *p, *yb, *qb, *kb, *vt, *hb, *wb;
    cudaGetSymbolAddress((void**)&s,   g_s);
    cudaGetSymbolAddress((void**)&att, g_att);
    cudaGetSymbolAddress((void**)&p,   g_p);
    cudaGetSymbolAddress((void**)&yb,  g_yb);
    cudaGetSymbolAddress((void**)&qb,  g_qb);
    cudaGetSymbolAddress((void**)&kb,  g_kb);
    cudaGetSymbolAddress((void**)&vt,  g_vt);
    cudaGetSymbolAddress((void**)&hb,  g_hb);
    cudaGetSymbolAddress((void**)&wb,  g_wb);
    bf16* wqTb = wb;
    bf16* wkTb = wb + (size_t)Dm * Dm;
    bf16* wvTb = wb + 2 * (size_t)Dm * Dm;
    bf16* f1b  = wb + 3 * (size_t)Dm * Dm;
    bf16* f2b  = wb + 4 * (size_t)Dm * Dm;

    const size_t sTD = (size_t)Tt * Dm;
    const size_t sTT = (size_t)Tt * Tt;
    const float scale = 1.0f / sqrtf((float)Dm);
    const int SMEM = 64 * 1024;

    cudaFuncSetAttribute(gemm_bf16<true,  false>, cudaFuncAttributeMaxDynamicSharedMemorySize, SMEM);
    cudaFuncSetAttribute(gemm_bf16<false, false>, cudaFuncAttributeMaxDynamicSharedMemorySize, SMEM);
    cudaFuncSetAttribute(gemm_bf16<true,  true >, cudaFuncAttributeMaxDynamicSharedMemorySize, SMEM);

    // 0. fused weight prep (1 launch)
    dim3 gprep(Dm / 32, Dm / 32, 5);
    prep_weights<<<gprep, 256>>>(wq, wk, wv, fc1_w, fc2_w, wb);

    // 1. LN1 -> yb (bf16)
    ln_kernel<<<MTOT, 256>>>(x, ln1_g, ln1_b, yb);

    // 2. Q, K projections: [16384,768] @ [768,768]^T -> bf16
    dim3 gproj(Dm / 128, MTOT / 128, 1);
    gemm_bf16<true, false><<<gproj, 256, SMEM>>>(yb, wqTb, 0, 0, qb, Dm, Dm, Dm, Dm, 0, 0, 0, 1.0f);
    gemm_bf16<true, false><<<gproj, 256, SMEM>>>(yb, wkTb, 0, 0, kb, Dm, Dm, Dm, Dm, 0, 0, 0, 1.0f);

    // 2b. vT = Wv^T @ Y^T directly: C[768, 16384] = wvTb[768,768] @ yb[16384,768]^T
    dim3 gvt(MTOT / 128, Dm / 128, 1);
    gemm_bf16<true, false><<<gvt, 256, SMEM>>>(wvTb, yb, 0, 0, vt, Dm, Dm, Dm, MTOT, 0, 0, 0, 1.0f);

    // 3. scores = scale * Q @ K^T -> fp32, per batch
    dim3 gsc(Tt / 128, Tt / 128, NB);
    gemm_bf16<false, false><<<gsc, 256, SMEM>>>(qb, kb, 0, 0, s, Dm, Dm, Dm, Tt, sTD, sTD, sTT, scale);

    // 4. softmax rows: fp32 -> bf16 probabilities
    softmax_kernel<<<NB * Tt, 256>>>(s, p);

    // 5. att = P @ V = P @ (vT)^T -> fp32  (B = vt rows [Dm], ldb = MTOT, batch offset Tt)
    dim3 gav(Dm / 128, Tt / 128, NB);
    gemm_bf16<false, false><<<gav, 256, SMEM>>>(p, vt, 0, 0, att, Tt, Tt, MTOT, Dm, sTT, (size_t)Tt, sTD, 1.0f);

    // 6. LN2 -> yb (bf16)
    ln_kernel<<<MTOT, 256>>>(att, ln2_g, ln2_b, yb);

    // 7. MLP fc1 (+bias, ReLU) -> bf16 h
    gemm_bf16<true, true><<<gproj, 256, SMEM>>>(yb, f1b, fc1_b, 0, hb, Dm, Dm, Dm, Dm, 0, 0, 0, 1.0f);

    // 8. MLP fc2 (+bias, +residual x) -> fp32 out
    gemm_bf16<false, false><<<gproj, 256, SMEM>>>(hb, f2b, fc2_b, x, out, Dm, Dm, Dm, Dm, 0, 0, 0, 1.0f);
}

// round 8
// speedup vs baseline: 7.8106x; 1.1109x over previous
#include <cuda_runtime.h>
#include <cuda_bf16.h>
#include <cstdint>
#include <math.h>

#define Dm   768
#define Tt   4096
#define NB   4
#define MTOT (NB * Tt)   // 16384

typedef __nv_bfloat16 bf16;

// ---------------- scratch (static __device__ — no allocations) ----------------
__device__ float g_s  [(size_t)NB * Tt * Tt];   // 256 MB fp32 scores
__device__ float g_att[MTOT * Dm];              // fp32 attention out
__device__ bf16  g_p  [(size_t)NB * Tt * Tt];   // 128 MB bf16 probabilities
__device__ bf16  g_yb [MTOT * Dm];              // LN out (bf16), reused LN1/LN2
__device__ bf16  g_qb [MTOT * Dm];
__device__ bf16  g_kb [MTOT * Dm];
__device__ bf16  g_vt [MTOT * Dm];              // vT: [Dm, MTOT]
__device__ bf16  g_hb [MTOT * Dm];
__device__ bf16  g_wb [5 * Dm * Dm];            // wqT, wkT, wvT, fc1w, fc2w (bf16)

// ================= helpers =================
__device__ __forceinline__ uint32_t smem_u32(const void* p) {
    uint32_t a;
    asm("{ .reg .u64 t; cvta.to.shared.u64 t, %1; cvt.u32.u64 %0, t; }" : "=r"(a) : "l"(p));
    return a;
}

#define CP_ASYNC16(dst, src) \
    asm volatile("cp.async.cg.shared.global [%0], [%1], 16;" :: "r"(dst), "l"(src))
#define CP_COMMIT() asm volatile("cp.async.commit_group;" ::: "memory")
#define CP_WAIT(n)  asm volatile("cp.async.wait_group %0;" :: "n"(n) : "memory")

#define MMA_BF16(d, a, b) \
    asm volatile("mma.sync.aligned.m16n8k16.row.col.f32.bf16.bf16.f32 " \
        "{%0,%1,%2,%3}, {%4,%5,%6,%7}, {%8,%9}, {%0,%1,%2,%3};" \
        : "+f"((d)[0]), "+f"((d)[1]), "+f"((d)[2]), "+f"((d)[3]) \
        : "r"((a)[0]), "r"((a)[1]), "r"((a)[2]), "r"((a)[3]), \
          "r"((b)[0]), "r"((b)[1]))

#define LDMX4(r0, r1, r2, r3, addr) \
    asm volatile("ldmatrix.sync.aligned.m8n8.x4.shared.b16 {%0,%1,%2,%3}, [%4];" \
        : "=r"(r0), "=r"(r1), "=r"(r2), "=r"(r3) : "r"(addr))

// swizzled BYTE offset inside a [128 rows x 128 bytes] tile
__device__ __forceinline__ int swb(int r, int cb) {
    return (r * 128 + cb) ^ ((r & 7) << 4);
}

// ================= bf16 mma.sync GEMM (ldmatrix fragments) =================
// NT: C[M,N] = alpha * A[M,K] @ B[N,K]^T  (+bias)(relu)(+res)
// 128 threads (2x2 warps), CTA tile 128x128, WARP tile 64x64, K-chunk 64, 2-stage cp.async.
// __launch_bounds__(128, 2): 256 regs/thread budget, 2 CTAs/SM.
template <bool OUTB, bool RELU>
__global__ __launch_bounds__(128, 2)
void gemm_bf16(const bf16* __restrict__ A, const bf16* __restrict__ B,
               const float* __restrict__ bias, const float* __restrict__ res,
               void* __restrict__ Cv, int K, int lda, int ldb, int ldc,
               size_t aS, size_t bS, size_t cS, float alpha)
{
    extern __shared__ char sm[];    // 2 stages x (A 16KB + B 16KB) = 64 KB
    const int tid  = threadIdx.x;
    const int w    = tid >> 5;
    const int lane = tid & 31;
    const int g    = lane >> 2;
    const int tig  = lane & 3;
    const int wm   = (w >> 1) * 64;   // warp M offset
    const int wn   = (w & 1) * 64;    // warp N offset
    const size_t bm = (size_t)blockIdx.y * 128;
    const size_t bn = (size_t)blockIdx.x * 128;
    const bf16* Ap = A + aS * blockIdx.z;
    const bf16* Bp = B + bS * blockIdx.z;

    // ldmatrix per-lane source coordinates
    const int lrA = (lane & 7) + ((lane >> 3) & 1) * 8;   // row within 16-row A block
    const int lcA = (lane >> 4) * 16;                     // 0 or 16 byte col
    const int lrB = (lane & 7) + ((lane >> 4) & 1) * 8;   // row within 16-row B block
    const int lcB = ((lane >> 3) & 1) * 16;

    float acc[4][8][4];
    #pragma unroll
    for (int i = 0; i < 4; i++)
        #pragma unroll
        for (int j = 0; j < 8; j++)
            #pragma unroll
            for (int t = 0; t < 4; t++) acc[i][j][t] = 0.f;

    char* Ast[2] = { sm,         sm + 32768 };
    char* Bst[2] = { sm + 16384, sm + 32768 + 16384 };
    const int nch = K >> 6;

    // ---- prologue: stage 0 (128 threads, 8 chunks of 16B each per tile) ----
    #pragma unroll
    for (int i = 0; i < 8; i++) {
        const int fidx = i * 128 + tid;       // 0..1023 chunks of 16B
        const int r  = fidx >> 3;
        const int c4 = fidx & 7;
        const int dst = r * 128 + ((c4 ^ (r & 7)) << 4);
        CP_ASYNC16(smem_u32(Ast[0] + dst), Ap + (bm + r) * (size_t)lda + c4 * 8);
        CP_ASYNC16(smem_u32(Bst[0] + dst), Bp + (bn + r) * (size_t)ldb + c4 * 8);
    }
    CP_COMMIT();

    for (int c = 0; c < nch; c++) {
        const int st = c & 1;
        if (c + 1 < nch) {
            const int k0 = (c + 1) << 6;
            char* An = Ast[st ^ 1];
            char* Bn = Bst[st ^ 1];
            #pragma unroll
            for (int i = 0; i < 8; i++) {
                const int fidx = i * 128 + tid;
                const int r  = fidx >> 3;
                const int c4 = fidx & 7;
                const int dst = r * 128 + ((c4 ^ (r & 7)) << 4);
                CP_ASYNC16(smem_u32(An + dst), Ap + (bm + r) * (size_t)lda + k0 + c4 * 8);
                CP_ASYNC16(smem_u32(Bn + dst), Bp + (bn + r) * (size_t)ldb + k0 + c4 * 8);
            }
            CP_COMMIT();
            CP_WAIT(1);
        } else {
            CP_WAIT(0);
        }
        __syncthreads();

        const char* Asm = Ast[st];
        const char* Bsm = Bst[st];
        #pragma unroll
        for (int ks = 0; ks < 4; ks++) {      // 4 x k16 steps per 64-K chunk
            const int cb0 = ks * 32;
            uint32_t af[4][4];
            uint32_t bfr[8][2];
            #pragma unroll
            for (int mt = 0; mt < 4; mt++) {
                const uint32_t aadr = smem_u32(Asm + swb(wm + mt * 16 + lrA, cb0 + lcA));
                LDMX4(af[mt][0], af[mt][1], af[mt][2], af[mt][3], aadr);
            }
            #pragma unroll
            for (int np = 0; np < 4; np++) {  // pair of n8-tiles per ldmatrix.x4
                const uint32_t badr = smem_u32(Bsm + swb(wn + np * 16 + lrB, cb0 + lcB));
                LDMX4(bfr[np * 2][0], bfr[np * 2][1], bfr[np * 2 + 1][0], bfr[np * 2 + 1][1], badr);
            }
            #pragma unroll
            for (int mt = 0; mt < 4; mt++)
                #pragma unroll
                for (int nt = 0; nt < 8; nt++)
                    MMA_BF16(acc[mt][nt], af[mt], bfr[nt]);
        }
        __syncthreads();
    }

    // ---- epilogue ----
    float* Cf = (float*)Cv + cS * blockIdx.z;
    bf16*  Cb = (bf16*)Cv  + cS * blockIdx.z;
    const float* Rb = res ? res + cS * blockIdx.z : (const float*)0;
    #pragma unroll
    for (int mt = 0; mt < 4; mt++) {
        #pragma unroll
        for (int nt = 0; nt < 8; nt++) {
            const size_t row0 = bm + wm + mt * 16 + g;
            const int    col  = (int)bn + wn + nt * 8 + tig * 2;
            float b0 = 0.f, b1 = 0.f;
            if (bias) { b0 = bias[col]; b1 = bias[col + 1]; }
            #pragma unroll
            for (int h = 0; h < 2; h++) {
                const size_t r = row0 + h * 8;
                float v0 = acc[mt][nt][h * 2 + 0] * alpha + b0;
                float v1 = acc[mt][nt][h * 2 + 1] * alpha + b1;
                if (RELU) { v0 = fmaxf(v0, 0.f); v1 = fmaxf(v1, 0.f); }
                if (Rb) {
                    v0 += Rb[r * (size_t)ldc + col];
                    v1 += Rb[r * (size_t)ldc + col + 1];
                }
                if (OUTB) {
                    __nv_bfloat162 o;
                    o.x = __float2bfloat16(v0);
                    o.y = __float2bfloat16(v1);
                    *(__nv_bfloat162*)(Cb + r * (size_t)ldc + col) = o;
                } else {
                    float2 o = make_float2(v0, v1);
                    *(float2*)(Cf + r * (size_t)ldc + col) = o;
                }
            }
        }
    }
}

// ================= fused weight prep: 3x transpose+cvt, 2x cvt =================
// grid (24, 24, 5), block 256 (32x8)
__global__ void prep_weights(const float* __restrict__ wq, const float* __restrict__ wk,
                             const float* __restrict__ wv, const float* __restrict__ f1,
                             const float* __restrict__ f2, bf16* __restrict__ wb)
{
    const int z = blockIdx.z;
    const float* src = (z == 0) ? wq : (z == 1) ? wk : (z == 2) ? wv : (z == 3) ? f1 : f2;
    bf16* dst = wb + (size_t)z * Dm * Dm;
    const int c0 = blockIdx.x * 32, r0 = blockIdx.y * 32;
    const int tx = threadIdx.x & 31, ty = threadIdx.x >> 5;
    if (z < 3) {
        __shared__ float t[32][33];
        #pragma unroll
        for (int i = ty; i < 32; i += 8)
            t[i][tx] = src[(size_t)(r0 + i) * Dm + c0 + tx];
        __syncthreads();
        #pragma unroll
        for (int i = ty; i < 32; i += 8)
            dst[(size_t)(c0 + i) * Dm + r0 + tx] = __float2bfloat16(t[tx][i]);
    } else {
        #pragma unroll
        for (int i = ty; i < 32; i += 8)
            dst[(size_t)(r0 + i) * Dm + c0 + tx] = __float2bfloat16(src[(size_t)(r0 + i) * Dm + c0 + tx]);
    }
}

// ---------------- block reductions (256 threads) ----------------
__device__ __forceinline__ float blockSum(float v) {
    __shared__ float red[8];
    #pragma unroll
    for (int o = 16; o > 0; o >>= 1) v += __shfl_xor_sync(0xffffffffu, v, o);
    __syncthreads();
    if ((threadIdx.x & 31) == 0) red[threadIdx.x >> 5] = v;
    __syncthreads();
    float r = red[0];
    #pragma unroll
    for (int i = 1; i < 8; i++) r += red[i];
    return r;
}
__device__ __forceinline__ float blockMax(float v) {
    __shared__ float redm[8];
    #pragma unroll
    for (int o = 16; o > 0; o >>= 1) v = fmaxf(v, __shfl_xor_sync(0xffffffffu, v, o));
    __syncthreads();
    if ((threadIdx.x & 31) == 0) redm[threadIdx.x >> 5] = v;
    __syncthreads();
    float r = redm[0];
    #pragma unroll
    for (int i = 1; i < 8; i++) r = fmaxf(r, redm[i]);
    return r;
}

// ---------------- LayerNorm (faithful to buggy reference), bf16 out ----------------
__global__ void ln_kernel(const float* __restrict__ x, const float* __restrict__ g,
                          const float* __restrict__ b, bf16* __restrict__ out) {
    size_t row = blockIdx.x;
    const float* xr = x + row * Dm;
    int tid = threadIdx.x;
    float v0 = xr[tid], v1 = xr[tid + 256], v2 = xr[tid + 512];
    float mu = blockSum(v0 + v1 + v2) * (1.0f / Dm);
    float d0 = v0 - mu, d1 = v1 - mu, d2 = v2 - mu;
    float var = blockSum(d0 * d0 + d1 * d1 + d2 * d2) * (1.0f / (Dm - 1));
    float c = mu / sqrtf(var);           // reference's bug, reproduced exactly
    bf16* orow = out + row * Dm;
    orow[tid]       = __float2bfloat16((v0 - c) * g[tid]       + b[tid]);
    orow[tid + 256] = __float2bfloat16((v1 - c) * g[tid + 256] + b[tid + 256]);
    orow[tid + 512] = __float2bfloat16((v2 - c) * g[tid + 512] + b[tid + 512]);
}

// ---------------- row softmax over 4096: fp32 in, bf16 out ----------------
__global__ void softmax_kernel(const float* __restrict__ S, bf16* __restrict__ P) {
    size_t row = blockIdx.x;
    const float* sr = S + row * (size_t)Tt;
    bf16* pr = P + row * (size_t)Tt;
    int tid = threadIdx.x;
    float v[16];
    float m = -1e30f;
    #pragma unroll
    for (int i = 0; i < 16; i++) { v[i] = sr[tid + i * 256]; m = fmaxf(m, v[i]); }
    m = blockMax(m);
    float s = 0.f;
    #pragma unroll
    for (int i = 0; i < 16; i++) { v[i] = __expf(v[i] - m); s += v[i]; }
    s = blockSum(s);
    float inv = 1.0f / s;
    #pragma unroll
    for (int i = 0; i < 16; i++) pr[tid + i * 256] = __float2bfloat16(v[i] * inv);
}

// ---------------- launch ----------------
extern "C" void kernel_launch(void* const* d_in, const int* in_sizes, int n_in,
                              void* d_out, int out_size) {
    const float* x     = (const float*)d_in[0];
    const float* ln1_g = (const float*)d_in[1];
    const float* ln1_b = (const float*)d_in[2];
    const float* wq    = (const float*)d_in[3];
    const float* wk    = (const float*)d_in[4];
    const float* wv    = (const float*)d_in[5];
    const float* ln2_g = (const float*)d_in[6];
    const float* ln2_b = (const float*)d_in[7];
    const float* fc1_w = (const float*)d_in[8];
    const float* fc1_b = (const float*)d_in[9];
    const float* fc2_w = (const float*)d_in[10];
    const float* fc2_b = (const float*)d_in[11];
    float* out = (float*)d_out;

    float *s, *att;
    bf16 *p, *yb, *qb, *kb, *vt, *hb, *wb;
    cudaGetSymbolAddress((void**)&s,   g_s);
    cudaGetSymbolAddress((void**)&att, g_att);
    cudaGetSymbolAddress((void**)&p,   g_p);
    cudaGetSymbolAddress((void**)&yb,  g_yb);
    cudaGetSymbolAddress((void**)&qb,  g_qb);
    cudaGetSymbolAddress((void**)&kb,  g_kb);
    cudaGetSymbolAddress((void**)&vt,  g_vt);
    cudaGetSymbolAddress((void**)&hb,  g_hb);
    cudaGetSymbolAddress((void**)&wb,  g_wb);
    bf16* wqTb = wb;
    bf16* wkTb = wb + (size_t)Dm * Dm;
    bf16* wvTb = wb + 2 * (size_t)Dm * Dm;
    bf16* f1b  = wb + 3 * (size_t)Dm * Dm;
    bf16* f2b  = wb + 4 * (size_t)Dm * Dm;

    const size_t sTD = (size_t)Tt * Dm;
    const size_t sTT = (size_t)Tt * Tt;
    const float scale = 1.0f / sqrtf((float)Dm);
    const int SMEM = 64 * 1024;

    cudaFuncSetAttribute(gemm_bf16<true,  false>, cudaFuncAttributeMaxDynamicSharedMemorySize, SMEM);
    cudaFuncSetAttribute(gemm_bf16<false, false>, cudaFuncAttributeMaxDynamicSharedMemorySize, SMEM);
    cudaFuncSetAttribute(gemm_bf16<true,  true >, cudaFuncAttributeMaxDynamicSharedMemorySize, SMEM);

    // 0. fused weight prep (1 launch)
    dim3 gprep(Dm / 32, Dm / 32, 5);
    prep_weights<<<gprep, 256>>>(wq, wk, wv, fc1_w, fc2_w, wb);

    // 1. LN1 -> yb (bf16)
    ln_kernel<<<MTOT, 256>>>(x, ln1_g, ln1_b, yb);

    // 2. Q, K projections: [16384,768] @ [768,768]^T -> bf16
    dim3 gproj(Dm / 128, MTOT / 128, 1);
    gemm_bf16<true, false><<<gproj, 128, SMEM>>>(yb, wqTb, 0, 0, qb, Dm, Dm, Dm, Dm, 0, 0, 0, 1.0f);
    gemm_bf16<true, false><<<gproj, 128, SMEM>>>(yb, wkTb, 0, 0, kb, Dm, Dm, Dm, Dm, 0, 0, 0, 1.0f);

    // 2b. vT = Wv^T @ Y^T directly: C[768, 16384] = wvTb[768,768] @ yb[16384,768]^T
    dim3 gvt(MTOT / 128, Dm / 128, 1);
    gemm_bf16<true, false><<<gvt, 128, SMEM>>>(wvTb, yb, 0, 0, vt, Dm, Dm, Dm, MTOT, 0, 0, 0, 1.0f);

    // 3. scores = scale * Q @ K^T -> fp32, per batch
    dim3 gsc(Tt / 128, Tt / 128, NB);
    gemm_bf16<false, false><<<gsc, 128, SMEM>>>(qb, kb, 0, 0, s, Dm, Dm, Dm, Tt, sTD, sTD, sTT, scale);

    // 4. softmax rows: fp32 -> bf16 probabilities
    softmax_kernel<<<NB * Tt, 256>>>(s, p);

    // 5. att = P @ V = P @ (vT)^T -> fp32  (B = vt rows [Dm], ldb = MTOT, batch offset Tt)
    dim3 gav(Dm / 128, Tt / 128, NB);
    gemm_bf16<false, false><<<gav, 128, SMEM>>>(p, vt, 0, 0, att, Tt, Tt, MTOT, Dm, sTT, (size_t)Tt, sTD, 1.0f);

    // 6. LN2 -> yb (bf16)
    ln_kernel<<<MTOT, 256>>>(att, ln2_g, ln2_b, yb);

    // 7. MLP fc1 (+bias, ReLU) -> bf16 h
    gemm_bf16<true, true><<<gproj, 128, SMEM>>>(yb, f1b, fc1_b, 0, hb, Dm, Dm, Dm, Dm, 0, 0, 0, 1.0f);

    // 8. MLP fc2 (+bias, +residual x) -> fp32 out
    gemm_bf16<false, false><<<gproj, 128, SMEM>>>(hb, f2b, fc2_b, x, out, Dm, Dm, Dm, Dm, 0, 0, 0, 1.0f);
}